// round 3
// baseline (speedup 1.0000x reference)
#include <cuda_runtime.h>
#include <cstdint>

#define N_NODES 100000
#define E_EDGES 1600000
#define F_IN    512
#define F_HID   128
#define F_OUT   40

// Scratch (allocation-free rule: __device__ globals)
__device__ float g_m1[(size_t)N_NODES * F_HID];    // X @ W1
__device__ float g_agg1[(size_t)N_NODES * F_HID];  // scatter-sum of layer 1
__device__ float g_m2[(size_t)N_NODES * F_OUT];    // relu(h) @ W2

// ---------------------------------------------------------------------------
// Zero the accumulation buffers (agg1 and d_out) each launch.
// ---------------------------------------------------------------------------
__global__ void zero_bufs(float4* __restrict__ out4) {
    const long n_agg4 = (long)N_NODES * F_HID / 4;   // 12.8M
    const long n_out4 = (long)N_NODES * F_OUT / 4;   // 1M
    long i = (long)blockIdx.x * blockDim.x + threadIdx.x;
    long stride = (long)gridDim.x * blockDim.x;
    float4 z = make_float4(0.f, 0.f, 0.f, 0.f);
    float4* agg4 = (float4*)g_agg1;
    for (long j = i; j < n_agg4; j += stride) agg4[j] = z;
    for (long j = i; j < n_out4; j += stride) out4[j] = z;
}

// ---------------------------------------------------------------------------
// GEMM1: g_m1[N,128] = X[N,512] @ W1[512,128]   (fp32 tiled)
// BM=128 BN=128 BK=16, 256 threads, 8x8 per thread
// ---------------------------------------------------------------------------
__global__ __launch_bounds__(256) void gemm1_kernel(
    const float* __restrict__ A, const float* __restrict__ B) {
    const int BK = 16;
    __shared__ float As[BK][128];   // transposed A tile
    __shared__ float Bs[BK][128];

    int tid = threadIdx.x;
    int mBase = blockIdx.x * 128;
    int ty = tid >> 4;         // 0..15
    int tx = tid & 15;         // 0..15

    float acc[8][8] = {};

    int aRow = tid >> 2;            // 0..63
    int aCol = (tid & 3) * 4;       // 0,4,8,12
    int bRow = tid >> 5;            // 0..7
    int bCol = (tid & 31) * 4;      // 0..124

    for (int kBase = 0; kBase < F_IN; kBase += BK) {
        #pragma unroll
        for (int s = 0; s < 2; s++) {
            int r = aRow + s * 64;
            int grow = mBase + r;
            float4 v = make_float4(0.f, 0.f, 0.f, 0.f);
            if (grow < N_NODES)
                v = *(const float4*)(A + (size_t)grow * F_IN + kBase + aCol);
            As[aCol + 0][r] = v.x;
            As[aCol + 1][r] = v.y;
            As[aCol + 2][r] = v.z;
            As[aCol + 3][r] = v.w;
        }
        #pragma unroll
        for (int s = 0; s < 2; s++) {
            int r = bRow + s * 8;
            float4 v = *(const float4*)(B + (size_t)(kBase + r) * F_HID + bCol);
            *(float4*)&Bs[r][bCol] = v;
        }
        __syncthreads();

        #pragma unroll
        for (int k = 0; k < BK; k++) {
            float ra[8], rb[8];
            #pragma unroll
            for (int i = 0; i < 8; i++) ra[i] = As[k][ty * 8 + i];
            #pragma unroll
            for (int j = 0; j < 8; j++) rb[j] = Bs[k][tx * 8 + j];
            #pragma unroll
            for (int i = 0; i < 8; i++)
                #pragma unroll
                for (int j = 0; j < 8; j++)
                    acc[i][j] += ra[i] * rb[j];
        }
        __syncthreads();
    }

    #pragma unroll
    for (int i = 0; i < 8; i++) {
        int row = mBase + ty * 8 + i;
        if (row < N_NODES) {
            #pragma unroll
            for (int j4 = 0; j4 < 2; j4++) {
                float4 v = make_float4(acc[i][j4 * 4 + 0], acc[i][j4 * 4 + 1],
                                       acc[i][j4 * 4 + 2], acc[i][j4 * 4 + 3]);
                *(float4*)(g_m1 + (size_t)row * F_HID + tx * 8 + j4 * 4) = v;
            }
        }
    }
}

// ---------------------------------------------------------------------------
// Scatter1: agg1[dst] += m1[src] * w  — one warp per edge, float4 red ops
// edge_index arrives as int32 (JAX canonicalizes int64 -> int32).
// ---------------------------------------------------------------------------
__global__ __launch_bounds__(256) void scatter1_kernel(
    const int* __restrict__ ei, const float* __restrict__ ew) {
    long long wid = (long long)blockIdx.x * (blockDim.x >> 5) + (threadIdx.x >> 5);
    int lane = threadIdx.x & 31;
    if (wid >= E_EDGES) return;
    int src = ei[wid];
    int dst = ei[E_EDGES + wid];
    float w = ew[wid];
    float4 v = ((const float4*)(g_m1 + (size_t)src * F_HID))[lane];
    v.x *= w; v.y *= w; v.z *= w; v.w *= w;
    float* daddr = g_agg1 + (size_t)dst * F_HID + lane * 4;
    asm volatile("red.global.add.v4.f32 [%0], {%1,%2,%3,%4};"
                 :: "l"(daddr), "f"(v.x), "f"(v.y), "f"(v.z), "f"(v.w)
                 : "memory");
}

// ---------------------------------------------------------------------------
// GEMM2 (fused relu + b1 on input):
//   g_m2[N,40] = relu(agg1 + b1) @ W2[128,40]
// Tile: 32 rows per block, W2 fully in smem. 256 threads -> thread computes
// (row = tid/8, 5 classes).
// ---------------------------------------------------------------------------
__global__ __launch_bounds__(256) void gemm2_kernel(
    const float* __restrict__ W2, const float* __restrict__ b1) {
    __shared__ float W2s[F_HID][F_OUT];   // 20 KB
    __shared__ float hs[32][132];         // padded stride, 16.9 KB
    __shared__ float b1s[F_HID];

    int tid = threadIdx.x;
    for (int i = tid; i < F_HID * F_OUT; i += 256)
        W2s[i / F_OUT][i % F_OUT] = W2[i];
    if (tid < F_HID) b1s[tid] = b1[tid];
    __syncthreads();

    int rowBase = blockIdx.x * 32;
    for (int i = tid; i < 32 * 32; i += 256) {   // 32 rows x 32 float4
        int r = i >> 5, c4 = i & 31;
        int row = rowBase + r;
        float4 v = make_float4(0.f, 0.f, 0.f, 0.f);
        if (row < N_NODES)
            v = ((const float4*)(g_agg1 + (size_t)row * F_HID))[c4];
        float* hp = &hs[r][c4 * 4];
        hp[0] = fmaxf(v.x + b1s[c4 * 4 + 0], 0.f);
        hp[1] = fmaxf(v.y + b1s[c4 * 4 + 1], 0.f);
        hp[2] = fmaxf(v.z + b1s[c4 * 4 + 2], 0.f);
        hp[3] = fmaxf(v.w + b1s[c4 * 4 + 3], 0.f);
    }
    __syncthreads();

    int r = tid >> 3;                 // 0..31
    int cbase = (tid & 7) * 5;        // 0,5,...,35
    float acc[5] = {0.f, 0.f, 0.f, 0.f, 0.f};
    #pragma unroll 8
    for (int k = 0; k < F_HID; k++) {
        float hv = hs[r][k];
        #pragma unroll
        for (int c = 0; c < 5; c++) acc[c] += hv * W2s[k][cbase + c];
    }
    int row = rowBase + r;
    if (row < N_NODES) {
        #pragma unroll
        for (int c = 0; c < 5; c++)
            g_m2[(size_t)row * F_OUT + cbase + c] = acc[c];
    }
}

// ---------------------------------------------------------------------------
// Scatter2: out[dst] += m2[src] * w  — 3 edges per warp (10 float4 lanes each)
// ---------------------------------------------------------------------------
__global__ __launch_bounds__(256) void scatter2_kernel(
    const int* __restrict__ ei, const float* __restrict__ ew,
    float* __restrict__ out) {
    long long wid = (long long)blockIdx.x * (blockDim.x >> 5) + (threadIdx.x >> 5);
    int lane = threadIdx.x & 31;
    int sub = lane / 10;        // 0,1,2 active; 3 idle
    int c4 = lane % 10;
    if (sub >= 3) return;
    long long e = wid * 3 + sub;
    if (e >= E_EDGES) return;
    int src = ei[e];
    int dst = ei[E_EDGES + e];
    float w = ew[e];
    float4 v = ((const float4*)(g_m2 + (size_t)src * F_OUT))[c4];
    v.x *= w; v.y *= w; v.z *= w; v.w *= w;
    float* daddr = out + (size_t)dst * F_OUT + c4 * 4;
    asm volatile("red.global.add.v4.f32 [%0], {%1,%2,%3,%4};"
                 :: "l"(daddr), "f"(v.x), "f"(v.y), "f"(v.z), "f"(v.w)
                 : "memory");
}

// ---------------------------------------------------------------------------
// log_softmax per row (plus b2), in-place on d_out. One warp per row.
// ---------------------------------------------------------------------------
__global__ __launch_bounds__(256) void logsoftmax_kernel(
    float* __restrict__ out, const float* __restrict__ b2) {
    int warpId = blockIdx.x * (blockDim.x >> 5) + (threadIdx.x >> 5);
    int lane = threadIdx.x & 31;
    if (warpId >= N_NODES) return;
    float* row = out + (size_t)warpId * F_OUT;

    float x0 = row[lane] + b2[lane];
    float x1 = (lane < 8) ? row[32 + lane] + b2[32 + lane] : -1e30f;

    float m = fmaxf(x0, x1);
    #pragma unroll
    for (int o = 16; o; o >>= 1) m = fmaxf(m, __shfl_xor_sync(0xFFFFFFFFu, m, o));

    float s = __expf(x0 - m) + ((lane < 8) ? __expf(x1 - m) : 0.f);
    #pragma unroll
    for (int o = 16; o; o >>= 1) s += __shfl_xor_sync(0xFFFFFFFFu, s, o);

    float lse = m + __logf(s);
    row[lane] = x0 - lse;
    if (lane < 8) row[32 + lane] = x1 - lse;
}

// ---------------------------------------------------------------------------
extern "C" void kernel_launch(void* const* d_in, const int* in_sizes, int n_in,
                              void* d_out, int out_size) {
    const float* X   = (const float*)d_in[0];        // [100000,512]
    const int*   EI  = (const int*)d_in[1];          // [2,1600000] int32
    const float* EW  = (const float*)d_in[2];        // [1600000]
    const float* W1  = (const float*)d_in[3];        // [512,128]
    const float* B1  = (const float*)d_in[4];        // [128]
    const float* W2  = (const float*)d_in[5];        // [128,40]
    const float* B2  = (const float*)d_in[6];        // [40]
    float*       OUT = (float*)d_out;                // [100000,40]

    // 1. zero accumulators (agg1 + d_out)
    zero_bufs<<<4096, 256>>>((float4*)OUT);

    // 2. GEMM1: m1 = X @ W1
    gemm1_kernel<<<(N_NODES + 127) / 128, 256>>>(X, W1);

    // 3. Scatter1: agg1[dst] += m1[src] * w   (warp per edge)
    {
        int warpsPerBlock = 256 / 32;
        long long nWarps = E_EDGES;
        int blocks = (int)((nWarps + warpsPerBlock - 1) / warpsPerBlock);
        scatter1_kernel<<<blocks, 256>>>(EI, EW);
    }

    // 4. GEMM2: m2 = relu(agg1 + b1) @ W2
    gemm2_kernel<<<(N_NODES + 31) / 32, 256>>>(W2, B1);

    // 5. Scatter2: out[dst] += m2[src] * w   (3 edges per warp)
    {
        long long nWarps = (E_EDGES + 2) / 3;
        int blocks = (int)((nWarps + 7) / 8);
        scatter2_kernel<<<blocks, 256>>>(EI, EW, OUT);
    }

    // 6. log_softmax rows (+ b2), in place
    logsoftmax_kernel<<<(N_NODES + 7) / 8, 256>>>(OUT, B2);
}

// round 6
// speedup vs baseline: 1.1717x; 1.1717x over previous
#include <cuda_runtime.h>
#include <cuda_bf16.h>
#include <cstdint>

#define N_NODES 100000
#define E_EDGES 1600000
#define F_IN    512
#define F_HID   128
#define F_OUT   40

// Scratch (allocation-free rule: __device__ globals)
__device__ float g_m1[(size_t)N_NODES * F_HID];    // X @ W1
__device__ float g_agg1[(size_t)N_NODES * F_HID];  // scatter-sum of layer 1
__device__ float g_m2[(size_t)N_NODES * F_OUT];    // relu(h) @ W2

// ============================================================================
// GEMM1 (mma.sync bf16, 3-term split): g_m1[N,128] = X[N,512] @ W1[512,128]
// Block tile 128x128, BK=32. 8 warps in 4(m) x 2(n); warp tile 32x64.
// Fragments m16n8k16; D = Ahi*Bhi + Ahi*Blo + Alo*Bhi (fp32 accum).
// ============================================================================

__device__ __forceinline__ void mma16816(float* d, const uint32_t* a,
                                         uint32_t b0, uint32_t b1) {
    asm volatile(
        "mma.sync.aligned.m16n8k16.row.col.f32.bf16.bf16.f32 "
        "{%0,%1,%2,%3}, {%4,%5,%6,%7}, {%8,%9}, {%0,%1,%2,%3};"
        : "+f"(d[0]), "+f"(d[1]), "+f"(d[2]), "+f"(d[3])
        : "r"(a[0]), "r"(a[1]), "r"(a[2]), "r"(a[3]), "r"(b0), "r"(b1));
}

__device__ __forceinline__ void split2(float x, float y,
                                       uint32_t& hi, uint32_t& lo) {
    __nv_bfloat162 h = __floats2bfloat162_rn(x, y);   // .x = low 16 bits
    float hx = __bfloat162float(h.x), hy = __bfloat162float(h.y);
    __nv_bfloat162 l = __floats2bfloat162_rn(x - hx, y - hy);
    hi = *(uint32_t*)&h;
    lo = *(uint32_t*)&l;
}

#define A_STRIDE 36   // 32 bf16 + 4 pad (72B rows, mild-conflict-free)
#define B_STRIDE 36

__global__ __launch_bounds__(256) void gemm1_mma(const float* __restrict__ X,
                                                 const float* __restrict__ W1) {
    __shared__ __align__(16) unsigned short Ahi[128 * A_STRIDE];
    __shared__ __align__(16) unsigned short Alo[128 * A_STRIDE];
    __shared__ __align__(16) unsigned short Bhi[128 * B_STRIDE];
    __shared__ __align__(16) unsigned short Blo[128 * B_STRIDE];

    int tid = threadIdx.x;
    int wid = tid >> 5, lane = tid & 31;
    int warp_m = wid >> 1;          // 0..3 -> rows warp_m*32
    int warp_n = wid & 1;           // 0..1 -> cols warp_n*64
    int g = lane >> 2, tg = lane & 3;
    int mBase = blockIdx.x * 128;

    float acc[2][8][4];
    #pragma unroll
    for (int mt = 0; mt < 2; mt++)
        #pragma unroll
        for (int nt = 0; nt < 8; nt++)
            #pragma unroll
            for (int i = 0; i < 4; i++) acc[mt][nt][i] = 0.f;

    for (int stage = 0; stage < 16; stage++) {
        int kBase = stage * 32;

        // ---- A tile: 128 rows x 32 k fp32 -> hi/lo bf16 ----
        #pragma unroll
        for (int i = 0; i < 4; i++) {
            int idx = tid + 256 * i;          // 0..1023 float4s
            int row = idx >> 3, k4 = idx & 7;
            int grow = mBase + row;
            float4 v = make_float4(0.f, 0.f, 0.f, 0.f);
            if (grow < N_NODES)
                v = *(const float4*)(X + (size_t)grow * F_IN + kBase + k4 * 4);
            uint32_t h0, l0, h1, l1;
            split2(v.x, v.y, h0, l0);
            split2(v.z, v.w, h1, l1);
            int si = row * A_STRIDE + k4 * 4;
            *(uint2*)&Ahi[si] = make_uint2(h0, h1);
            *(uint2*)&Alo[si] = make_uint2(l0, l1);
        }
        // ---- B tile: W1[kBase..+31][0..127] -> [n][k] hi/lo bf16 ----
        #pragma unroll
        for (int i = 0; i < 8; i++) {
            int p = tid + 256 * i;            // 0..2047 k-pairs
            int n = p & 127, k2 = p >> 7;     // k2: 0..15
            float w0 = W1[(size_t)(kBase + 2 * k2) * F_HID + n];
            float w1 = W1[(size_t)(kBase + 2 * k2 + 1) * F_HID + n];
            uint32_t bh, bl;
            split2(w0, w1, bh, bl);
            int si = n * B_STRIDE + 2 * k2;
            *(uint32_t*)&Bhi[si] = bh;
            *(uint32_t*)&Blo[si] = bl;
        }
        __syncthreads();

        // ---- compute: 2 k16 sub-steps ----
        #pragma unroll
        for (int ks = 0; ks < 2; ks++) {
            int kk = ks * 16;
            uint32_t ah[2][4], al[2][4];
            #pragma unroll
            for (int mt = 0; mt < 2; mt++) {
                int base = (warp_m * 32 + mt * 16 + g) * A_STRIDE + kk + 2 * tg;
                ah[mt][0] = *(uint32_t*)&Ahi[base];
                ah[mt][1] = *(uint32_t*)&Ahi[base + 8 * A_STRIDE];
                ah[mt][2] = *(uint32_t*)&Ahi[base + 8];
                ah[mt][3] = *(uint32_t*)&Ahi[base + 8 * A_STRIDE + 8];
                al[mt][0] = *(uint32_t*)&Alo[base];
                al[mt][1] = *(uint32_t*)&Alo[base + 8 * A_STRIDE];
                al[mt][2] = *(uint32_t*)&Alo[base + 8];
                al[mt][3] = *(uint32_t*)&Alo[base + 8 * A_STRIDE + 8];
            }
            #pragma unroll
            for (int nt = 0; nt < 8; nt++) {
                int bbase = (warp_n * 64 + nt * 8 + g) * B_STRIDE + kk + 2 * tg;
                uint32_t bh0 = *(uint32_t*)&Bhi[bbase];
                uint32_t bh1 = *(uint32_t*)&Bhi[bbase + 8];
                uint32_t bl0 = *(uint32_t*)&Blo[bbase];
                uint32_t bl1 = *(uint32_t*)&Blo[bbase + 8];
                #pragma unroll
                for (int mt = 0; mt < 2; mt++) {
                    mma16816(acc[mt][nt], ah[mt], bh0, bh1);  // hi*hi
                    mma16816(acc[mt][nt], ah[mt], bl0, bl1);  // hi*lo
                    mma16816(acc[mt][nt], al[mt], bh0, bh1);  // lo*hi
                }
            }
        }
        __syncthreads();
    }

    // ---- epilogue: D frag (c0,c1)@(row g, col 2tg), (c2,c3)@(row g+8) ----
    #pragma unroll
    for (int mt = 0; mt < 2; mt++) {
        int r0 = mBase + warp_m * 32 + mt * 16 + g;
        int r1 = r0 + 8;
        #pragma unroll
        for (int nt = 0; nt < 8; nt++) {
            int col = warp_n * 64 + nt * 8 + 2 * tg;
            if (r0 < N_NODES)
                *(float2*)(g_m1 + (size_t)r0 * F_HID + col) =
                    make_float2(acc[mt][nt][0], acc[mt][nt][1]);
            if (r1 < N_NODES)
                *(float2*)(g_m1 + (size_t)r1 * F_HID + col) =
                    make_float2(acc[mt][nt][2], acc[mt][nt][3]);
        }
    }
}

// ============================================================================
// Scatter1: agg1[dst] += m1[src] * w  — one warp per edge, float4 red ops
// ============================================================================
__global__ __launch_bounds__(256) void scatter1_kernel(
    const int* __restrict__ ei, const float* __restrict__ ew) {
    long long wid = (long long)blockIdx.x * (blockDim.x >> 5) + (threadIdx.x >> 5);
    int lane = threadIdx.x & 31;
    if (wid >= E_EDGES) return;
    int src = ei[wid];
    int dst = ei[E_EDGES + wid];
    float w = ew[wid];
    float4 v = ((const float4*)(g_m1 + (size_t)src * F_HID))[lane];
    v.x *= w; v.y *= w; v.z *= w; v.w *= w;
    float* daddr = g_agg1 + (size_t)dst * F_HID + lane * 4;
    asm volatile("red.global.add.v4.f32 [%0], {%1,%2,%3,%4};"
                 :: "l"(daddr), "f"(v.x), "f"(v.y), "f"(v.z), "f"(v.w)
                 : "memory");
}

// ============================================================================
// GEMM2: g_m2[N,40] = relu(agg1 + b1) @ W2[128,40]
// 128 rows/block, 2 threads per row (k-split 64+64), 40 fp32 acc/thread.
// ============================================================================
#define G2_SMEM ((5120 + 128 + 128 * 132) * 4)   // 88576 bytes

__global__ __launch_bounds__(256) void gemm2_kernel(const float* __restrict__ W2,
                                                    const float* __restrict__ b1) {
    extern __shared__ float dsm[];
    float* W2s = dsm;                 // [128][40]
    float* b1s = dsm + 5120;          // [128]
    float* hs  = dsm + 5248;          // [128][132]

    int tid = threadIdx.x;
    for (int i = tid; i < F_HID * F_OUT; i += 256) W2s[i] = W2[i];
    if (tid < F_HID) b1s[tid] = b1[tid];
    __syncthreads();

    int rowBase = blockIdx.x * 128;
    for (int idx = tid; idx < 128 * 32; idx += 256) {
        int r = idx >> 5, c4 = idx & 31;
        int row = rowBase + r;
        float4 v = make_float4(0.f, 0.f, 0.f, 0.f);
        if (row < N_NODES)
            v = ((const float4*)(g_agg1 + (size_t)row * F_HID))[c4];
        float* hp = &hs[r * 132 + c4 * 4];
        hp[0] = fmaxf(v.x + b1s[c4 * 4 + 0], 0.f);
        hp[1] = fmaxf(v.y + b1s[c4 * 4 + 1], 0.f);
        hp[2] = fmaxf(v.z + b1s[c4 * 4 + 2], 0.f);
        hp[3] = fmaxf(v.w + b1s[c4 * 4 + 3], 0.f);
    }
    __syncthreads();

    int r = tid >> 1;
    int half = tid & 1;
    const float* hrow = &hs[r * 132 + half * 64];
    const float* w2h = W2s + half * 64 * F_OUT;
    float acc[40];
    #pragma unroll
    for (int c = 0; c < 40; c++) acc[c] = 0.f;
    #pragma unroll 4
    for (int k = 0; k < 64; k++) {
        float hv = hrow[k];
        const float4* wr = (const float4*)(w2h + k * F_OUT);
        #pragma unroll
        for (int c = 0; c < 10; c++) {
            float4 w = wr[c];
            acc[c * 4 + 0] += hv * w.x;
            acc[c * 4 + 1] += hv * w.y;
            acc[c * 4 + 2] += hv * w.z;
            acc[c * 4 + 3] += hv * w.w;
        }
    }
    __syncthreads();                  // hs fully consumed
    float* red = hs;                  // [128][41]
    if (half) {
        #pragma unroll
        for (int c = 0; c < 40; c++) red[r * 41 + c] = acc[c];
    }
    __syncthreads();
    if (!half) {
        #pragma unroll
        for (int c = 0; c < 40; c++) red[r * 41 + c] += acc[c];
    }
    __syncthreads();

    int nValid = min(128, N_NODES - rowBase);
    for (int idx = tid; idx < 128 * 10; idx += 256) {
        int rr = idx / 10, c4 = idx % 10;
        if (rr < nValid) {
            float4 v = make_float4(red[rr * 41 + c4 * 4 + 0], red[rr * 41 + c4 * 4 + 1],
                                   red[rr * 41 + c4 * 4 + 2], red[rr * 41 + c4 * 4 + 3]);
            *(float4*)(g_m2 + (size_t)(rowBase + rr) * F_OUT + c4 * 4) = v;
        }
    }
}

// ============================================================================
// Scatter2: out[dst] += m2[src] * w  — 3 edges per warp (10 float4 lanes each)
// ============================================================================
__global__ __launch_bounds__(256) void scatter2_kernel(
    const int* __restrict__ ei, const float* __restrict__ ew,
    float* __restrict__ out) {
    long long wid = (long long)blockIdx.x * (blockDim.x >> 5) + (threadIdx.x >> 5);
    int lane = threadIdx.x & 31;
    int sub = lane / 10;
    int c4 = lane % 10;
    if (sub >= 3) return;
    long long e = wid * 3 + sub;
    if (e >= E_EDGES) return;
    int src = ei[e];
    int dst = ei[E_EDGES + e];
    float w = ew[e];
    float4 v = ((const float4*)(g_m2 + (size_t)src * F_OUT))[c4];
    v.x *= w; v.y *= w; v.z *= w; v.w *= w;
    float* daddr = out + (size_t)dst * F_OUT + c4 * 4;
    asm volatile("red.global.add.v4.f32 [%0], {%1,%2,%3,%4};"
                 :: "l"(daddr), "f"(v.x), "f"(v.y), "f"(v.z), "f"(v.w)
                 : "memory");
}

// ============================================================================
// log_softmax per row (plus b2), in-place on d_out. One warp per row.
// ============================================================================
__global__ __launch_bounds__(256) void logsoftmax_kernel(
    float* __restrict__ out, const float* __restrict__ b2) {
    int warpId = blockIdx.x * (blockDim.x >> 5) + (threadIdx.x >> 5);
    int lane = threadIdx.x & 31;
    if (warpId >= N_NODES) return;
    float* row = out + (size_t)warpId * F_OUT;

    float x0 = row[lane] + b2[lane];
    float x1 = (lane < 8) ? row[32 + lane] + b2[32 + lane] : -1e30f;

    float m = fmaxf(x0, x1);
    #pragma unroll
    for (int o = 16; o; o >>= 1) m = fmaxf(m, __shfl_xor_sync(0xFFFFFFFFu, m, o));

    float s = __expf(x0 - m) + ((lane < 8) ? __expf(x1 - m) : 0.f);
    #pragma unroll
    for (int o = 16; o; o >>= 1) s += __shfl_xor_sync(0xFFFFFFFFu, s, o);

    float lse = m + __logf(s);
    row[lane] = x0 - lse;
    if (lane < 8) row[32 + lane] = x1 - lse;
}

// ============================================================================
extern "C" void kernel_launch(void* const* d_in, const int* in_sizes, int n_in,
                              void* d_out, int out_size) {
    const float* X   = (const float*)d_in[0];        // [100000,512]
    const int*   EI  = (const int*)d_in[1];          // [2,1600000] int32
    const float* EW  = (const float*)d_in[2];        // [1600000]
    const float* W1  = (const float*)d_in[3];        // [512,128]
    const float* B1  = (const float*)d_in[4];        // [128]
    const float* W2  = (const float*)d_in[5];        // [128,40]
    const float* B2  = (const float*)d_in[6];        // [40]
    float*       OUT = (float*)d_out;                // [100000,40]

    cudaFuncSetAttribute(gemm2_kernel, cudaFuncAttributeMaxDynamicSharedMemorySize,
                         G2_SMEM);

    // 1. zero accumulators via memset nodes
    void* aggPtr = nullptr;
    cudaGetSymbolAddress(&aggPtr, g_agg1);
    cudaMemsetAsync(aggPtr, 0, (size_t)N_NODES * F_HID * sizeof(float));
    cudaMemsetAsync(OUT, 0, (size_t)out_size * sizeof(float));

    // 2. GEMM1 (tensor mma bf16 split): m1 = X @ W1
    gemm1_mma<<<(N_NODES + 127) / 128, 256>>>(X, W1);

    // 3. Scatter1: agg1[dst] += m1[src] * w   (warp per edge)
    {
        long long nWarps = E_EDGES;
        int blocks = (int)((nWarps + 7) / 8);
        scatter1_kernel<<<blocks, 256>>>(EI, EW);
    }

    // 4. GEMM2: m2 = relu(agg1 + b1) @ W2
    gemm2_kernel<<<(N_NODES + 127) / 128, 256, G2_SMEM>>>(W2, B1);

    // 5. Scatter2: out[dst] += m2[src] * w   (3 edges per warp)
    {
        long long nWarps = (E_EDGES + 2) / 3;
        int blocks = (int)((nWarps + 7) / 8);
        scatter2_kernel<<<blocks, 256>>>(EI, EW, OUT);
    }

    // 6. log_softmax rows (+ b2), in place
    logsoftmax_kernel<<<(N_NODES + 7) / 8, 256>>>(OUT, B2);
}

// round 7
// speedup vs baseline: 1.4541x; 1.2410x over previous
#include <cuda_runtime.h>
#include <cuda_bf16.h>
#include <cstdint>

#define N_NODES 100000
#define E_EDGES 1600000
#define F_IN    512
#define F_HID   128
#define F_OUT   40

// Scratch (allocation-free rule: __device__ globals)
__device__ float g_m1[(size_t)N_NODES * F_HID];    // X @ W1
__device__ float g_agg1[(size_t)N_NODES * F_HID];  // relu(scatter-sum + b1)
__device__ float g_m2[(size_t)N_NODES * F_OUT];    // h @ W2

// CSR binning scratch (rebuilt every launch)
__device__ int   g_deg[N_NODES];
__device__ int   g_off[N_NODES];
__device__ int   g_cur[N_NODES];
__device__ int   g_bsum[128];
__device__ int   g_bscan[128];
__device__ int   g_esrc[E_EDGES];
__device__ float g_ewp[E_EDGES];

// ============================================================================
// GEMM1 (mma.sync bf16, 3-term split): g_m1[N,128] = X[N,512] @ W1[512,128]
// ============================================================================
__device__ __forceinline__ void mma16816(float* d, const uint32_t* a,
                                         uint32_t b0, uint32_t b1) {
    asm volatile(
        "mma.sync.aligned.m16n8k16.row.col.f32.bf16.bf16.f32 "
        "{%0,%1,%2,%3}, {%4,%5,%6,%7}, {%8,%9}, {%0,%1,%2,%3};"
        : "+f"(d[0]), "+f"(d[1]), "+f"(d[2]), "+f"(d[3])
        : "r"(a[0]), "r"(a[1]), "r"(a[2]), "r"(a[3]), "r"(b0), "r"(b1));
}

__device__ __forceinline__ void split2(float x, float y,
                                       uint32_t& hi, uint32_t& lo) {
    __nv_bfloat162 h = __floats2bfloat162_rn(x, y);
    float hx = __bfloat162float(h.x), hy = __bfloat162float(h.y);
    __nv_bfloat162 l = __floats2bfloat162_rn(x - hx, y - hy);
    hi = *(uint32_t*)&h;
    lo = *(uint32_t*)&l;
}

#define A_STRIDE 36
#define B_STRIDE 36

__global__ __launch_bounds__(256) void gemm1_mma(const float* __restrict__ X,
                                                 const float* __restrict__ W1) {
    __shared__ __align__(16) unsigned short Ahi[128 * A_STRIDE];
    __shared__ __align__(16) unsigned short Alo[128 * A_STRIDE];
    __shared__ __align__(16) unsigned short Bhi[128 * B_STRIDE];
    __shared__ __align__(16) unsigned short Blo[128 * B_STRIDE];

    int tid = threadIdx.x;
    int wid = tid >> 5, lane = tid & 31;
    int warp_m = wid >> 1;
    int warp_n = wid & 1;
    int g = lane >> 2, tg = lane & 3;
    int mBase = blockIdx.x * 128;

    float acc[2][8][4];
    #pragma unroll
    for (int mt = 0; mt < 2; mt++)
        #pragma unroll
        for (int nt = 0; nt < 8; nt++)
            #pragma unroll
            for (int i = 0; i < 4; i++) acc[mt][nt][i] = 0.f;

    for (int stage = 0; stage < 16; stage++) {
        int kBase = stage * 32;

        #pragma unroll
        for (int i = 0; i < 4; i++) {
            int idx = tid + 256 * i;
            int row = idx >> 3, k4 = idx & 7;
            int grow = mBase + row;
            float4 v = make_float4(0.f, 0.f, 0.f, 0.f);
            if (grow < N_NODES)
                v = *(const float4*)(X + (size_t)grow * F_IN + kBase + k4 * 4);
            uint32_t h0, l0, h1, l1;
            split2(v.x, v.y, h0, l0);
            split2(v.z, v.w, h1, l1);
            int si = row * A_STRIDE + k4 * 4;
            *(uint2*)&Ahi[si] = make_uint2(h0, h1);
            *(uint2*)&Alo[si] = make_uint2(l0, l1);
        }
        #pragma unroll
        for (int i = 0; i < 8; i++) {
            int p = tid + 256 * i;
            int n = p & 127, k2 = p >> 7;
            float w0 = W1[(size_t)(kBase + 2 * k2) * F_HID + n];
            float w1 = W1[(size_t)(kBase + 2 * k2 + 1) * F_HID + n];
            uint32_t bh, bl;
            split2(w0, w1, bh, bl);
            int si = n * B_STRIDE + 2 * k2;
            *(uint32_t*)&Bhi[si] = bh;
            *(uint32_t*)&Blo[si] = bl;
        }
        __syncthreads();

        #pragma unroll
        for (int ks = 0; ks < 2; ks++) {
            int kk = ks * 16;
            uint32_t ah[2][4], al[2][4];
            #pragma unroll
            for (int mt = 0; mt < 2; mt++) {
                int base = (warp_m * 32 + mt * 16 + g) * A_STRIDE + kk + 2 * tg;
                ah[mt][0] = *(uint32_t*)&Ahi[base];
                ah[mt][1] = *(uint32_t*)&Ahi[base + 8 * A_STRIDE];
                ah[mt][2] = *(uint32_t*)&Ahi[base + 8];
                ah[mt][3] = *(uint32_t*)&Ahi[base + 8 * A_STRIDE + 8];
                al[mt][0] = *(uint32_t*)&Alo[base];
                al[mt][1] = *(uint32_t*)&Alo[base + 8 * A_STRIDE];
                al[mt][2] = *(uint32_t*)&Alo[base + 8];
                al[mt][3] = *(uint32_t*)&Alo[base + 8 * A_STRIDE + 8];
            }
            #pragma unroll
            for (int nt = 0; nt < 8; nt++) {
                int bbase = (warp_n * 64 + nt * 8 + g) * B_STRIDE + kk + 2 * tg;
                uint32_t bh0 = *(uint32_t*)&Bhi[bbase];
                uint32_t bh1 = *(uint32_t*)&Bhi[bbase + 8];
                uint32_t bl0 = *(uint32_t*)&Blo[bbase];
                uint32_t bl1 = *(uint32_t*)&Blo[bbase + 8];
                #pragma unroll
                for (int mt = 0; mt < 2; mt++) {
                    mma16816(acc[mt][nt], ah[mt], bh0, bh1);
                    mma16816(acc[mt][nt], ah[mt], bl0, bl1);
                    mma16816(acc[mt][nt], al[mt], bh0, bh1);
                }
            }
        }
        __syncthreads();
    }

    #pragma unroll
    for (int mt = 0; mt < 2; mt++) {
        int r0 = mBase + warp_m * 32 + mt * 16 + g;
        int r1 = r0 + 8;
        #pragma unroll
        for (int nt = 0; nt < 8; nt++) {
            int col = warp_n * 64 + nt * 8 + 2 * tg;
            if (r0 < N_NODES)
                *(float2*)(g_m1 + (size_t)r0 * F_HID + col) =
                    make_float2(acc[mt][nt][0], acc[mt][nt][1]);
            if (r1 < N_NODES)
                *(float2*)(g_m1 + (size_t)r1 * F_HID + col) =
                    make_float2(acc[mt][nt][2], acc[mt][nt][3]);
        }
    }
}

// ============================================================================
// CSR binning: histogram -> exclusive scan -> placement
// ============================================================================
__global__ __launch_bounds__(256) void bin_count(const int* __restrict__ ei) {
    int e = blockIdx.x * 256 + threadIdx.x;
    if (e < E_EDGES) atomicAdd(&g_deg[ei[E_EDGES + e]], 1);
}

// 98 blocks x 1024 elements: per-block exclusive scan + block totals
__global__ __launch_bounds__(256) void scanA() {
    __shared__ int wsum[8];
    int t = threadIdx.x;
    int base = blockIdx.x * 1024 + t * 4;
    int v[4];
    #pragma unroll
    for (int i = 0; i < 4; i++)
        v[i] = (base + i < N_NODES) ? g_deg[base + i] : 0;
    int s = v[0] + v[1] + v[2] + v[3];
    int lane = t & 31, w = t >> 5;
    int inc = s;
    #pragma unroll
    for (int o = 1; o < 32; o <<= 1) {
        int n = __shfl_up_sync(0xFFFFFFFFu, inc, o);
        if (lane >= o) inc += n;
    }
    if (lane == 31) wsum[w] = inc;
    __syncthreads();
    if (t == 0) {
        int run = 0;
        #pragma unroll
        for (int i = 0; i < 8; i++) { int x = wsum[i]; wsum[i] = run; run += x; }
        g_bsum[blockIdx.x] = run;
    }
    __syncthreads();
    int excl = inc - s + wsum[w];
    int o0 = excl, o1 = o0 + v[0], o2 = o1 + v[1], o3 = o2 + v[2];
    if (base + 0 < N_NODES) g_off[base + 0] = o0;
    if (base + 1 < N_NODES) g_off[base + 1] = o1;
    if (base + 2 < N_NODES) g_off[base + 2] = o2;
    if (base + 3 < N_NODES) g_off[base + 3] = o3;
}

__global__ void scanB(int nb) {
    if (threadIdx.x == 0) {
        int run = 0;
        for (int i = 0; i < nb; i++) { int x = g_bsum[i]; g_bscan[i] = run; run += x; }
    }
}

__global__ __launch_bounds__(256) void scanC() {
    int add = g_bscan[blockIdx.x];
    int base = blockIdx.x * 1024 + threadIdx.x;
    #pragma unroll
    for (int i = 0; i < 4; i++) {
        int idx = base + i * 256;
        if (idx < N_NODES) {
            int val = g_off[idx] + add;
            g_off[idx] = val;
            g_cur[idx] = val;
        }
    }
}

__global__ __launch_bounds__(256) void bin_fill(const int* __restrict__ ei,
                                                const float* __restrict__ ew) {
    int e = blockIdx.x * 256 + threadIdx.x;
    if (e >= E_EDGES) return;
    int src = ei[e];
    int dst = ei[E_EDGES + e];
    int pos = atomicAdd(&g_cur[dst], 1);
    g_esrc[pos] = src;
    g_ewp[pos] = ew[e];
}

// ============================================================================
// Agg1 (dst-driven, fused b1+relu): agg1[v] = relu(sum_j m1[src_j]*w_j + b1)
// One warp per node; lane holds 4 floats (float4).
// ============================================================================
__global__ __launch_bounds__(256) void agg1_kernel(const float* __restrict__ b1) {
    int wv = blockIdx.x * 8 + (threadIdx.x >> 5);
    int lane = threadIdx.x & 31;
    if (wv >= N_NODES) return;
    int beg = g_off[wv];
    int end = (wv == N_NODES - 1) ? E_EDGES : g_off[wv + 1];

    float4 a0 = make_float4(0.f, 0.f, 0.f, 0.f);
    float4 a1 = make_float4(0.f, 0.f, 0.f, 0.f);
    int j = beg;
    for (; j + 2 <= end; j += 2) {
        int s0 = g_esrc[j], s1 = g_esrc[j + 1];
        float w0 = g_ewp[j], w1 = g_ewp[j + 1];
        float4 m0 = ((const float4*)(g_m1 + (size_t)s0 * F_HID))[lane];
        float4 m1v = ((const float4*)(g_m1 + (size_t)s1 * F_HID))[lane];
        a0.x += m0.x * w0; a0.y += m0.y * w0; a0.z += m0.z * w0; a0.w += m0.w * w0;
        a1.x += m1v.x * w1; a1.y += m1v.y * w1; a1.z += m1v.z * w1; a1.w += m1v.w * w1;
    }
    if (j < end) {
        int s0 = g_esrc[j];
        float w0 = g_ewp[j];
        float4 m0 = ((const float4*)(g_m1 + (size_t)s0 * F_HID))[lane];
        a0.x += m0.x * w0; a0.y += m0.y * w0; a0.z += m0.z * w0; a0.w += m0.w * w0;
    }
    float4 bb = ((const float4*)b1)[lane];
    float4 r;
    r.x = fmaxf(a0.x + a1.x + bb.x, 0.f);
    r.y = fmaxf(a0.y + a1.y + bb.y, 0.f);
    r.z = fmaxf(a0.z + a1.z + bb.z, 0.f);
    r.w = fmaxf(a0.w + a1.w + bb.w, 0.f);
    ((float4*)(g_agg1 + (size_t)wv * F_HID))[lane] = r;
}

// ============================================================================
// GEMM2: g_m2[N,40] = agg1 @ W2[128,40]   (agg1 already has relu+b1)
// ============================================================================
#define G2_SMEM ((5120 + 128 * 132) * 4)

__global__ __launch_bounds__(256) void gemm2_kernel(const float* __restrict__ W2) {
    extern __shared__ float dsm[];
    float* W2s = dsm;                 // [128][40]
    float* hs  = dsm + 5120;          // [128][132]

    int tid = threadIdx.x;
    for (int i = tid; i < F_HID * F_OUT; i += 256) W2s[i] = W2[i];
    __syncthreads();

    int rowBase = blockIdx.x * 128;
    for (int idx = tid; idx < 128 * 32; idx += 256) {
        int r = idx >> 5, c4 = idx & 31;
        int row = rowBase + r;
        float4 v = make_float4(0.f, 0.f, 0.f, 0.f);
        if (row < N_NODES)
            v = ((const float4*)(g_agg1 + (size_t)row * F_HID))[c4];
        *(float4*)&hs[r * 132 + c4 * 4] = v;
    }
    __syncthreads();

    int r = tid >> 1;
    int half = tid & 1;
    const float* hrow = &hs[r * 132 + half * 64];
    const float* w2h = W2s + half * 64 * F_OUT;
    float acc[40];
    #pragma unroll
    for (int c = 0; c < 40; c++) acc[c] = 0.f;
    #pragma unroll 4
    for (int k = 0; k < 64; k++) {
        float hv = hrow[k];
        const float4* wr = (const float4*)(w2h + k * F_OUT);
        #pragma unroll
        for (int c = 0; c < 10; c++) {
            float4 w = wr[c];
            acc[c * 4 + 0] += hv * w.x;
            acc[c * 4 + 1] += hv * w.y;
            acc[c * 4 + 2] += hv * w.z;
            acc[c * 4 + 3] += hv * w.w;
        }
    }
    __syncthreads();
    float* red = hs;                  // [128][41]
    if (half) {
        #pragma unroll
        for (int c = 0; c < 40; c++) red[r * 41 + c] = acc[c];
    }
    __syncthreads();
    if (!half) {
        #pragma unroll
        for (int c = 0; c < 40; c++) red[r * 41 + c] += acc[c];
    }
    __syncthreads();

    int nValid = min(128, N_NODES - rowBase);
    for (int idx = tid; idx < 128 * 10; idx += 256) {
        int rr = idx / 10, c4 = idx % 10;
        if (rr < nValid) {
            float4 v = make_float4(red[rr * 41 + c4 * 4 + 0], red[rr * 41 + c4 * 4 + 1],
                                   red[rr * 41 + c4 * 4 + 2], red[rr * 41 + c4 * 4 + 3]);
            *(float4*)(g_m2 + (size_t)(rowBase + rr) * F_OUT + c4 * 4) = v;
        }
    }
}

// ============================================================================
// Agg2 + b2 + log_softmax fused (dst-driven): one warp per node,
// lanes 0..9 hold float4 of the 40-wide row.
// ============================================================================
__global__ __launch_bounds__(256) void agg2_ls_kernel(const float* __restrict__ b2,
                                                      float* __restrict__ out) {
    int wv = blockIdx.x * 8 + (threadIdx.x >> 5);
    int lane = threadIdx.x & 31;
    if (wv >= N_NODES) return;
    int beg = g_off[wv];
    int end = (wv == N_NODES - 1) ? E_EDGES : g_off[wv + 1];
    bool act = lane < 10;

    float4 a0 = make_float4(0.f, 0.f, 0.f, 0.f);
    float4 a1 = make_float4(0.f, 0.f, 0.f, 0.f);
    int j = beg;
    for (; j + 2 <= end; j += 2) {
        int s0 = g_esrc[j], s1 = g_esrc[j + 1];
        float w0 = g_ewp[j], w1 = g_ewp[j + 1];
        if (act) {
            float4 m0 = ((const float4*)(g_m2 + (size_t)s0 * F_OUT))[lane];
            float4 m1v = ((const float4*)(g_m2 + (size_t)s1 * F_OUT))[lane];
            a0.x += m0.x * w0; a0.y += m0.y * w0; a0.z += m0.z * w0; a0.w += m0.w * w0;
            a1.x += m1v.x * w1; a1.y += m1v.y * w1; a1.z += m1v.z * w1; a1.w += m1v.w * w1;
        }
    }
    if (j < end) {
        int s0 = g_esrc[j];
        float w0 = g_ewp[j];
        if (act) {
            float4 m0 = ((const float4*)(g_m2 + (size_t)s0 * F_OUT))[lane];
            a0.x += m0.x * w0; a0.y += m0.y * w0; a0.z += m0.z * w0; a0.w += m0.w * w0;
        }
    }
    float4 x = make_float4(a0.x + a1.x, a0.y + a1.y, a0.z + a1.z, a0.w + a1.w);
    if (act) {
        float4 bb = ((const float4*)b2)[lane];
        x.x += bb.x; x.y += bb.y; x.z += bb.z; x.w += bb.w;
    }

    float m = act ? fmaxf(fmaxf(x.x, x.y), fmaxf(x.z, x.w)) : -1e30f;
    #pragma unroll
    for (int o = 16; o; o >>= 1) m = fmaxf(m, __shfl_xor_sync(0xFFFFFFFFu, m, o));

    float s = act ? (__expf(x.x - m) + __expf(x.y - m) +
                     __expf(x.z - m) + __expf(x.w - m)) : 0.f;
    #pragma unroll
    for (int o = 16; o; o >>= 1) s += __shfl_xor_sync(0xFFFFFFFFu, s, o);

    float lse = m + __logf(s);
    if (act) {
        x.x -= lse; x.y -= lse; x.z -= lse; x.w -= lse;
        ((float4*)(out + (size_t)wv * F_OUT))[lane] = x;
    }
}

// ============================================================================
extern "C" void kernel_launch(void* const* d_in, const int* in_sizes, int n_in,
                              void* d_out, int out_size) {
    const float* X   = (const float*)d_in[0];        // [100000,512]
    const int*   EI  = (const int*)d_in[1];          // [2,1600000] int32
    const float* EW  = (const float*)d_in[2];        // [1600000]
    const float* W1  = (const float*)d_in[3];        // [512,128]
    const float* B1  = (const float*)d_in[4];        // [128]
    const float* W2  = (const float*)d_in[5];        // [128,40]
    const float* B2  = (const float*)d_in[6];        // [40]
    float*       OUT = (float*)d_out;                // [100000,40]

    cudaFuncSetAttribute(gemm2_kernel, cudaFuncAttributeMaxDynamicSharedMemorySize,
                         G2_SMEM);

    const int NB_SCAN = (N_NODES + 1023) / 1024;     // 98
    const int EB = E_EDGES / 256;                    // 6250 (exact)

    // 0. zero degree histogram
    void* degPtr = nullptr;
    cudaGetSymbolAddress(&degPtr, g_deg);
    cudaMemsetAsync(degPtr, 0, N_NODES * sizeof(int));

    // 1. GEMM1 (tensor mma bf16 split): m1 = X @ W1
    gemm1_mma<<<(N_NODES + 127) / 128, 256>>>(X, W1);

    // 2. CSR binning (shared by both layers)
    bin_count<<<EB, 256>>>(EI);
    scanA<<<NB_SCAN, 256>>>();
    scanB<<<1, 32>>>(NB_SCAN);
    scanC<<<NB_SCAN, 256>>>();
    bin_fill<<<EB, 256>>>(EI, EW);

    // 3. Agg1 (fused b1 + relu): agg1 = relu(S(m1) + b1)
    agg1_kernel<<<(N_NODES + 7) / 8, 256>>>(B1);

    // 4. GEMM2: m2 = agg1 @ W2
    gemm2_kernel<<<(N_NODES + 127) / 128, 256, G2_SMEM>>>(W2);

    // 5. Agg2 + b2 + log_softmax fused, writes d_out
    agg2_ls_kernel<<<(N_NODES + 7) / 8, 256>>>(B2, OUT);
}

// round 8
// speedup vs baseline: 1.6637x; 1.1441x over previous
#include <cuda_runtime.h>
#include <cuda_bf16.h>
#include <cstdint>

#define N_NODES 100000
#define E_EDGES 1600000
#define F_IN    512
#define F_HID   128
#define F_OUT   40

// Scratch (allocation-free rule: __device__ globals)
__device__ float g_m1[(size_t)N_NODES * F_HID];    // X @ W1
__device__ float g_agg1[(size_t)N_NODES * F_HID];  // relu(scatter-sum + b1)
__device__ float g_m2[(size_t)N_NODES * F_OUT];    // h @ W2

// W1 bf16 split, pair-packed: [k2][n] uint32 = (bf16(W[2k2][n]), bf16(W[2k2+1][n]))
__device__ uint32_t g_w1hi[256 * 128];
__device__ uint32_t g_w1lo[256 * 128];

// CSR binning scratch (rebuilt every launch)
__device__ int   g_deg[N_NODES];
__device__ int   g_off[N_NODES];
__device__ int   g_cur[N_NODES];
__device__ int   g_bsum[128];
__device__ int   g_bscan[128];
__device__ int   g_esrc[E_EDGES];
__device__ float g_ewp[E_EDGES];

// ============================================================================
// helpers
// ============================================================================
__device__ __forceinline__ void mma16816(float* d, const uint32_t* a,
                                         uint32_t b0, uint32_t b1) {
    asm volatile(
        "mma.sync.aligned.m16n8k16.row.col.f32.bf16.bf16.f32 "
        "{%0,%1,%2,%3}, {%4,%5,%6,%7}, {%8,%9}, {%0,%1,%2,%3};"
        : "+f"(d[0]), "+f"(d[1]), "+f"(d[2]), "+f"(d[3])
        : "r"(a[0]), "r"(a[1]), "r"(a[2]), "r"(a[3]), "r"(b0), "r"(b1));
}

__device__ __forceinline__ void split2(float x, float y,
                                       uint32_t& hi, uint32_t& lo) {
    __nv_bfloat162 h = __floats2bfloat162_rn(x, y);
    float hx = __bfloat162float(h.x), hy = __bfloat162float(h.y);
    __nv_bfloat162 l = __floats2bfloat162_rn(x - hx, y - hy);
    hi = *(uint32_t*)&h;
    lo = *(uint32_t*)&l;
}

// ============================================================================
// prep_w1: split W1 once into pair-packed bf16 hi/lo  (32768 elements)
// ============================================================================
__global__ __launch_bounds__(256) void prep_w1(const float* __restrict__ W1) {
    int i = blockIdx.x * 256 + threadIdx.x;   // i = k2*128 + n
    int k2 = i >> 7, n = i & 127;
    float w0 = W1[(size_t)(2 * k2) * F_HID + n];
    float w1 = W1[(size_t)(2 * k2 + 1) * F_HID + n];
    uint32_t hi, lo;
    split2(w0, w1, hi, lo);
    g_w1hi[i] = hi;
    g_w1lo[i] = lo;
}

// ============================================================================
// GEMM1 (mma.sync bf16, 3-term split): g_m1[N,128] = X[N,512] @ W1[512,128]
// Block 128x128, BK=32, 8 warps (4m x 2n), software-pipelined global loads.
// ============================================================================
#define A_STRIDE 36
#define B_STRIDE 36

__global__ __launch_bounds__(256) void gemm1_mma(const float* __restrict__ X) {
    __shared__ __align__(16) unsigned short Ahi[128 * A_STRIDE];
    __shared__ __align__(16) unsigned short Alo[128 * A_STRIDE];
    __shared__ __align__(16) unsigned short Bhi[128 * B_STRIDE];
    __shared__ __align__(16) unsigned short Blo[128 * B_STRIDE];

    int tid = threadIdx.x;
    int wid = tid >> 5, lane = tid & 31;
    int warp_m = wid >> 1;
    int warp_n = wid & 1;
    int g = lane >> 2, tg = lane & 3;
    int mBase = blockIdx.x * 128;

    // A-tile addressing: thread loads 4 float4s (rows tid>>3 + 32*i)
    int aRow = tid >> 3, aK4 = tid & 7;
    bool aValid[4];
    const float* aPtr[4];
    #pragma unroll
    for (int i = 0; i < 4; i++) {
        int row = aRow + 32 * i;
        int grow = mBase + row;
        aValid[i] = grow < N_NODES;
        aPtr[i] = X + (size_t)(aValid[i] ? grow : 0) * F_IN + aK4 * 4;
    }
    // B-tile addressing: thread loads 8 uint32 pairs: p = tid + 256*i
    int bN = tid & 127, bK2 = tid >> 7;   // k2 local = bK2 + 2*i

    float acc[2][8][4];
    #pragma unroll
    for (int mt = 0; mt < 2; mt++)
        #pragma unroll
        for (int nt = 0; nt < 8; nt++)
            #pragma unroll
            for (int i = 0; i < 4; i++) acc[mt][nt][i] = 0.f;

    // --- prologue: load stage 0 into regs ---
    float4 aReg[4];
    uint32_t bRegH[8], bRegL[8];
    #pragma unroll
    for (int i = 0; i < 4; i++)
        aReg[i] = aValid[i] ? *(const float4*)(aPtr[i])
                            : make_float4(0.f, 0.f, 0.f, 0.f);
    #pragma unroll
    for (int i = 0; i < 8; i++) {
        int idx = (bK2 + 2 * i) * 128 + bN;
        bRegH[i] = g_w1hi[idx];
        bRegL[i] = g_w1lo[idx];
    }

    for (int stage = 0; stage < 16; stage++) {
        // --- store regs -> smem (with A split) ---
        #pragma unroll
        for (int i = 0; i < 4; i++) {
            uint32_t h0, l0, h1, l1;
            split2(aReg[i].x, aReg[i].y, h0, l0);
            split2(aReg[i].z, aReg[i].w, h1, l1);
            int si = (aRow + 32 * i) * A_STRIDE + aK4 * 4;
            *(uint2*)&Ahi[si] = make_uint2(h0, h1);
            *(uint2*)&Alo[si] = make_uint2(l0, l1);
        }
        #pragma unroll
        for (int i = 0; i < 8; i++) {
            int si = bN * B_STRIDE + 2 * (bK2 + 2 * i);
            *(uint32_t*)&Bhi[si] = bRegH[i];
            *(uint32_t*)&Blo[si] = bRegL[i];
        }
        __syncthreads();

        // --- prefetch next stage ---
        if (stage < 15) {
            int kBase = (stage + 1) * 32;
            #pragma unroll
            for (int i = 0; i < 4; i++)
                aReg[i] = aValid[i] ? *(const float4*)(aPtr[i] + kBase)
                                    : make_float4(0.f, 0.f, 0.f, 0.f);
            #pragma unroll
            for (int i = 0; i < 8; i++) {
                int idx = (kBase / 2 + bK2 + 2 * i) * 128 + bN;
                bRegH[i] = g_w1hi[idx];
                bRegL[i] = g_w1lo[idx];
            }
        }

        // --- compute from smem ---
        #pragma unroll
        for (int ks = 0; ks < 2; ks++) {
            int kk = ks * 16;
            uint32_t ah[2][4], al[2][4];
            #pragma unroll
            for (int mt = 0; mt < 2; mt++) {
                int base = (warp_m * 32 + mt * 16 + g) * A_STRIDE + kk + 2 * tg;
                ah[mt][0] = *(uint32_t*)&Ahi[base];
                ah[mt][1] = *(uint32_t*)&Ahi[base + 8 * A_STRIDE];
                ah[mt][2] = *(uint32_t*)&Ahi[base + 8];
                ah[mt][3] = *(uint32_t*)&Ahi[base + 8 * A_STRIDE + 8];
                al[mt][0] = *(uint32_t*)&Alo[base];
                al[mt][1] = *(uint32_t*)&Alo[base + 8 * A_STRIDE];
                al[mt][2] = *(uint32_t*)&Alo[base + 8];
                al[mt][3] = *(uint32_t*)&Alo[base + 8 * A_STRIDE + 8];
            }
            #pragma unroll
            for (int nt = 0; nt < 8; nt++) {
                int bbase = (warp_n * 64 + nt * 8 + g) * B_STRIDE + kk + 2 * tg;
                uint32_t bh0 = *(uint32_t*)&Bhi[bbase];
                uint32_t bh1 = *(uint32_t*)&Bhi[bbase + 8];
                uint32_t bl0 = *(uint32_t*)&Blo[bbase];
                uint32_t bl1 = *(uint32_t*)&Blo[bbase + 8];
                #pragma unroll
                for (int mt = 0; mt < 2; mt++) {
                    mma16816(acc[mt][nt], ah[mt], bh0, bh1);
                    mma16816(acc[mt][nt], ah[mt], bl0, bl1);
                    mma16816(acc[mt][nt], al[mt], bh0, bh1);
                }
            }
        }
        __syncthreads();
    }

    #pragma unroll
    for (int mt = 0; mt < 2; mt++) {
        int r0 = mBase + warp_m * 32 + mt * 16 + g;
        int r1 = r0 + 8;
        #pragma unroll
        for (int nt = 0; nt < 8; nt++) {
            int col = warp_n * 64 + nt * 8 + 2 * tg;
            if (r0 < N_NODES)
                *(float2*)(g_m1 + (size_t)r0 * F_HID + col) =
                    make_float2(acc[mt][nt][0], acc[mt][nt][1]);
            if (r1 < N_NODES)
                *(float2*)(g_m1 + (size_t)r1 * F_HID + col) =
                    make_float2(acc[mt][nt][2], acc[mt][nt][3]);
        }
    }
}

// ============================================================================
// CSR binning: histogram -> exclusive scan -> placement
// ============================================================================
__global__ __launch_bounds__(256) void bin_count(const int* __restrict__ ei) {
    int e = blockIdx.x * 256 + threadIdx.x;
    if (e < E_EDGES) atomicAdd(&g_deg[ei[E_EDGES + e]], 1);
}

__global__ __launch_bounds__(256) void scanA() {
    __shared__ int wsum[8];
    int t = threadIdx.x;
    int base = blockIdx.x * 1024 + t * 4;
    int v[4];
    #pragma unroll
    for (int i = 0; i < 4; i++)
        v[i] = (base + i < N_NODES) ? g_deg[base + i] : 0;
    int s = v[0] + v[1] + v[2] + v[3];
    int lane = t & 31, w = t >> 5;
    int inc = s;
    #pragma unroll
    for (int o = 1; o < 32; o <<= 1) {
        int n = __shfl_up_sync(0xFFFFFFFFu, inc, o);
        if (lane >= o) inc += n;
    }
    if (lane == 31) wsum[w] = inc;
    __syncthreads();
    if (t == 0) {
        int run = 0;
        #pragma unroll
        for (int i = 0; i < 8; i++) { int x = wsum[i]; wsum[i] = run; run += x; }
        g_bsum[blockIdx.x] = run;
    }
    __syncthreads();
    int excl = inc - s + wsum[w];
    int o0 = excl, o1 = o0 + v[0], o2 = o1 + v[1], o3 = o2 + v[2];
    if (base + 0 < N_NODES) g_off[base + 0] = o0;
    if (base + 1 < N_NODES) g_off[base + 1] = o1;
    if (base + 2 < N_NODES) g_off[base + 2] = o2;
    if (base + 3 < N_NODES) g_off[base + 3] = o3;
}

// parallel scan of <=128 block sums (one block of 128 threads)
__global__ __launch_bounds__(128) void scanB(int nb) {
    __shared__ int ws[4];
    int t = threadIdx.x;
    int v = (t < nb) ? g_bsum[t] : 0;
    int lane = t & 31, w = t >> 5;
    int inc = v;
    #pragma unroll
    for (int o = 1; o < 32; o <<= 1) {
        int n = __shfl_up_sync(0xFFFFFFFFu, inc, o);
        if (lane >= o) inc += n;
    }
    if (lane == 31) ws[w] = inc;
    __syncthreads();
    if (t == 0) {
        int run = 0;
        #pragma unroll
        for (int i = 0; i < 4; i++) { int x = ws[i]; ws[i] = run; run += x; }
    }
    __syncthreads();
    if (t < nb) g_bscan[t] = inc - v + ws[w];
}

__global__ __launch_bounds__(256) void scanC() {
    int add = g_bscan[blockIdx.x];
    int base = blockIdx.x * 1024 + threadIdx.x;
    #pragma unroll
    for (int i = 0; i < 4; i++) {
        int idx = base + i * 256;
        if (idx < N_NODES) {
            int val = g_off[idx] + add;
            g_off[idx] = val;
            g_cur[idx] = val;
        }
    }
}

__global__ __launch_bounds__(256) void bin_fill(const int* __restrict__ ei,
                                                const float* __restrict__ ew) {
    int e = blockIdx.x * 256 + threadIdx.x;
    if (e >= E_EDGES) return;
    int src = ei[e];
    int dst = ei[E_EDGES + e];
    int pos = atomicAdd(&g_cur[dst], 1);
    g_esrc[pos] = src;
    g_ewp[pos] = ew[e];
}

// ============================================================================
// Agg1 (dst-driven, fused b1+relu), 4-deep unroll for MLP
// ============================================================================
__global__ __launch_bounds__(256) void agg1_kernel(const float* __restrict__ b1) {
    int wv = blockIdx.x * 8 + (threadIdx.x >> 5);
    int lane = threadIdx.x & 31;
    if (wv >= N_NODES) return;
    int beg = g_off[wv];
    int end = (wv == N_NODES - 1) ? E_EDGES : g_off[wv + 1];

    float4 a0 = make_float4(0.f, 0.f, 0.f, 0.f);
    float4 a1 = make_float4(0.f, 0.f, 0.f, 0.f);
    float4 a2 = make_float4(0.f, 0.f, 0.f, 0.f);
    float4 a3 = make_float4(0.f, 0.f, 0.f, 0.f);
    int j = beg;
    for (; j + 4 <= end; j += 4) {
        int s0 = g_esrc[j], s1 = g_esrc[j + 1], s2 = g_esrc[j + 2], s3 = g_esrc[j + 3];
        float w0 = g_ewp[j], w1 = g_ewp[j + 1], w2 = g_ewp[j + 2], w3 = g_ewp[j + 3];
        float4 m0 = ((const float4*)(g_m1 + (size_t)s0 * F_HID))[lane];
        float4 m1v = ((const float4*)(g_m1 + (size_t)s1 * F_HID))[lane];
        float4 m2v = ((const float4*)(g_m1 + (size_t)s2 * F_HID))[lane];
        float4 m3v = ((const float4*)(g_m1 + (size_t)s3 * F_HID))[lane];
        a0.x += m0.x * w0; a0.y += m0.y * w0; a0.z += m0.z * w0; a0.w += m0.w * w0;
        a1.x += m1v.x * w1; a1.y += m1v.y * w1; a1.z += m1v.z * w1; a1.w += m1v.w * w1;
        a2.x += m2v.x * w2; a2.y += m2v.y * w2; a2.z += m2v.z * w2; a2.w += m2v.w * w2;
        a3.x += m3v.x * w3; a3.y += m3v.y * w3; a3.z += m3v.z * w3; a3.w += m3v.w * w3;
    }
    for (; j < end; j++) {
        int s0 = g_esrc[j];
        float w0 = g_ewp[j];
        float4 m0 = ((const float4*)(g_m1 + (size_t)s0 * F_HID))[lane];
        a0.x += m0.x * w0; a0.y += m0.y * w0; a0.z += m0.z * w0; a0.w += m0.w * w0;
    }
    float4 bb = ((const float4*)b1)[lane];
    float4 r;
    r.x = fmaxf(a0.x + a1.x + a2.x + a3.x + bb.x, 0.f);
    r.y = fmaxf(a0.y + a1.y + a2.y + a3.y + bb.y, 0.f);
    r.z = fmaxf(a0.z + a1.z + a2.z + a3.z + bb.z, 0.f);
    r.w = fmaxf(a0.w + a1.w + a2.w + a3.w + bb.w, 0.f);
    ((float4*)(g_agg1 + (size_t)wv * F_HID))[lane] = r;
}

// ============================================================================
// GEMM2: g_m2[N,40] = agg1 @ W2[128,40]
// ============================================================================
#define G2_SMEM ((5120 + 128 * 132) * 4)

__global__ __launch_bounds__(256) void gemm2_kernel(const float* __restrict__ W2) {
    extern __shared__ float dsm[];
    float* W2s = dsm;                 // [128][40]
    float* hs  = dsm + 5120;          // [128][132]

    int tid = threadIdx.x;
    for (int i = tid; i < F_HID * F_OUT; i += 256) W2s[i] = W2[i];
    __syncthreads();

    int rowBase = blockIdx.x * 128;
    for (int idx = tid; idx < 128 * 32; idx += 256) {
        int r = idx >> 5, c4 = idx & 31;
        int row = rowBase + r;
        float4 v = make_float4(0.f, 0.f, 0.f, 0.f);
        if (row < N_NODES)
            v = ((const float4*)(g_agg1 + (size_t)row * F_HID))[c4];
        *(float4*)&hs[r * 132 + c4 * 4] = v;
    }
    __syncthreads();

    int r = tid >> 1;
    int half = tid & 1;
    const float* hrow = &hs[r * 132 + half * 64];
    const float* w2h = W2s + half * 64 * F_OUT;
    float acc[40];
    #pragma unroll
    for (int c = 0; c < 40; c++) acc[c] = 0.f;
    #pragma unroll 4
    for (int k = 0; k < 64; k++) {
        float hv = hrow[k];
        const float4* wr = (const float4*)(w2h + k * F_OUT);
        #pragma unroll
        for (int c = 0; c < 10; c++) {
            float4 w = wr[c];
            acc[c * 4 + 0] += hv * w.x;
            acc[c * 4 + 1] += hv * w.y;
            acc[c * 4 + 2] += hv * w.z;
            acc[c * 4 + 3] += hv * w.w;
        }
    }
    __syncthreads();
    float* red = hs;                  // [128][41]
    if (half) {
        #pragma unroll
        for (int c = 0; c < 40; c++) red[r * 41 + c] = acc[c];
    }
    __syncthreads();
    if (!half) {
        #pragma unroll
        for (int c = 0; c < 40; c++) red[r * 41 + c] += acc[c];
    }
    __syncthreads();

    int nValid = min(128, N_NODES - rowBase);
    for (int idx = tid; idx < 128 * 10; idx += 256) {
        int rr = idx / 10, c4 = idx % 10;
        if (rr < nValid) {
            float4 v = make_float4(red[rr * 41 + c4 * 4 + 0], red[rr * 41 + c4 * 4 + 1],
                                   red[rr * 41 + c4 * 4 + 2], red[rr * 41 + c4 * 4 + 3]);
            *(float4*)(g_m2 + (size_t)(rowBase + rr) * F_OUT + c4 * 4) = v;
        }
    }
}

// ============================================================================
// Agg2 + b2 + log_softmax fused (dst-driven)
// ============================================================================
__global__ __launch_bounds__(256) void agg2_ls_kernel(const float* __restrict__ b2,
                                                      float* __restrict__ out) {
    int wv = blockIdx.x * 8 + (threadIdx.x >> 5);
    int lane = threadIdx.x & 31;
    if (wv >= N_NODES) return;
    int beg = g_off[wv];
    int end = (wv == N_NODES - 1) ? E_EDGES : g_off[wv + 1];
    bool act = lane < 10;

    float4 a0 = make_float4(0.f, 0.f, 0.f, 0.f);
    float4 a1 = make_float4(0.f, 0.f, 0.f, 0.f);
    int j = beg;
    for (; j + 2 <= end; j += 2) {
        int s0 = g_esrc[j], s1 = g_esrc[j + 1];
        float w0 = g_ewp[j], w1 = g_ewp[j + 1];
        if (act) {
            float4 m0 = ((const float4*)(g_m2 + (size_t)s0 * F_OUT))[lane];
            float4 m1v = ((const float4*)(g_m2 + (size_t)s1 * F_OUT))[lane];
            a0.x += m0.x * w0; a0.y += m0.y * w0; a0.z += m0.z * w0; a0.w += m0.w * w0;
            a1.x += m1v.x * w1; a1.y += m1v.y * w1; a1.z += m1v.z * w1; a1.w += m1v.w * w1;
        }
    }
    if (j < end) {
        int s0 = g_esrc[j];
        float w0 = g_ewp[j];
        if (act) {
            float4 m0 = ((const float4*)(g_m2 + (size_t)s0 * F_OUT))[lane];
            a0.x += m0.x * w0; a0.y += m0.y * w0; a0.z += m0.z * w0; a0.w += m0.w * w0;
        }
    }
    float4 x = make_float4(a0.x + a1.x, a0.y + a1.y, a0.z + a1.z, a0.w + a1.w);
    if (act) {
        float4 bb = ((const float4*)b2)[lane];
        x.x += bb.x; x.y += bb.y; x.z += bb.z; x.w += bb.w;
    }

    float m = act ? fmaxf(fmaxf(x.x, x.y), fmaxf(x.z, x.w)) : -1e30f;
    #pragma unroll
    for (int o = 16; o; o >>= 1) m = fmaxf(m, __shfl_xor_sync(0xFFFFFFFFu, m, o));

    float s = act ? (__expf(x.x - m) + __expf(x.y - m) +
                     __expf(x.z - m) + __expf(x.w - m)) : 0.f;
    #pragma unroll
    for (int o = 16; o; o >>= 1) s += __shfl_xor_sync(0xFFFFFFFFu, s, o);

    float lse = m + __logf(s);
    if (act) {
        x.x -= lse; x.y -= lse; x.z -= lse; x.w -= lse;
        ((float4*)(out + (size_t)wv * F_OUT))[lane] = x;
    }
}

// ============================================================================
extern "C" void kernel_launch(void* const* d_in, const int* in_sizes, int n_in,
                              void* d_out, int out_size) {
    const float* X   = (const float*)d_in[0];        // [100000,512]
    const int*   EI  = (const int*)d_in[1];          // [2,1600000] int32
    const float* EW  = (const float*)d_in[2];        // [1600000]
    const float* W1  = (const float*)d_in[3];        // [512,128]
    const float* B1  = (const float*)d_in[4];        // [128]
    const float* W2  = (const float*)d_in[5];        // [128,40]
    const float* B2  = (const float*)d_in[6];        // [40]
    float*       OUT = (float*)d_out;                // [100000,40]

    cudaFuncSetAttribute(gemm2_kernel, cudaFuncAttributeMaxDynamicSharedMemorySize,
                         G2_SMEM);

    const int NB_SCAN = (N_NODES + 1023) / 1024;     // 98
    const int EB = E_EDGES / 256;                    // 6250 (exact)

    // 0. zero degree histogram + split W1
    void* degPtr = nullptr;
    cudaGetSymbolAddress(&degPtr, g_deg);
    cudaMemsetAsync(degPtr, 0, N_NODES * sizeof(int));
    prep_w1<<<128, 256>>>(W1);

    // 1. GEMM1 (tensor mma bf16 split): m1 = X @ W1
    gemm1_mma<<<(N_NODES + 127) / 128, 256>>>(X);

    // 2. CSR binning (shared by both layers)
    bin_count<<<EB, 256>>>(EI);
    scanA<<<NB_SCAN, 256>>>();
    scanB<<<1, 128>>>(NB_SCAN);
    scanC<<<NB_SCAN, 256>>>();
    bin_fill<<<EB, 256>>>(EI, EW);

    // 3. Agg1 (fused b1 + relu): agg1 = relu(S(m1) + b1)
    agg1_kernel<<<(N_NODES + 7) / 8, 256>>>(B1);

    // 4. GEMM2: m2 = agg1 @ W2
    gemm2_kernel<<<(N_NODES + 127) / 128, 256, G2_SMEM>>>(W2);

    // 5. Agg2 + b2 + log_softmax fused, writes d_out
    agg2_ls_kernel<<<(N_NODES + 7) / 8, 256>>>(B2, OUT);
}

// round 9
// speedup vs baseline: 1.7438x; 1.0482x over previous
#include <cuda_runtime.h>
#include <cuda_fp16.h>
#include <cstdint>

#define N_NODES 100000
#define E_EDGES 1600000
#define F_IN    512
#define F_HID   128
#define F_OUT   40

// Scratch (allocation-free rule: __device__ globals)
__device__ float g_m1[(size_t)N_NODES * F_HID];    // X @ W1
__device__ float g_agg1[(size_t)N_NODES * F_HID];  // relu(scatter-sum + b1)
__device__ float g_m2[(size_t)N_NODES * F_OUT];    // h @ W2

// W1 fp16, pair-packed: [k2][n] uint32 = (fp16(W[2k2][n]), fp16(W[2k2+1][n]))
__device__ uint32_t g_w1h[256 * 128];

// CSR binning scratch (rebuilt every launch)
__device__ int   g_deg[N_NODES];
__device__ int   g_off[N_NODES];
__device__ int   g_cur[N_NODES];
__device__ int   g_bsum[128];
__device__ int   g_bscan[128];
__device__ int   g_esrc[E_EDGES];
__device__ float g_ewp[E_EDGES];

// ============================================================================
// helpers
// ============================================================================
__device__ __forceinline__ void mma16816h(float* d, const uint32_t* a,
                                          uint32_t b0, uint32_t b1) {
    asm volatile(
        "mma.sync.aligned.m16n8k16.row.col.f32.f16.f16.f32 "
        "{%0,%1,%2,%3}, {%4,%5,%6,%7}, {%8,%9}, {%0,%1,%2,%3};"
        : "+f"(d[0]), "+f"(d[1]), "+f"(d[2]), "+f"(d[3])
        : "r"(a[0]), "r"(a[1]), "r"(a[2]), "r"(a[3]), "r"(b0), "r"(b1));
}

// fp16 hi/lo split of a pair of floats (packed half2 as uint32)
__device__ __forceinline__ void split2h(float x, float y,
                                        uint32_t& hi, uint32_t& lo) {
    __half2 h = __floats2half2_rn(x, y);
    float hx = __half2float(__low2half(h)), hy = __half2float(__high2half(h));
    __half2 l = __floats2half2_rn(x - hx, y - hy);
    hi = *(uint32_t*)&h;
    lo = *(uint32_t*)&l;
}

// ============================================================================
// prep_w1: round W1 once to pair-packed fp16  (32768 elements)
// ============================================================================
__global__ __launch_bounds__(256) void prep_w1(const float* __restrict__ W1) {
    int i = blockIdx.x * 256 + threadIdx.x;   // i = k2*128 + n
    int k2 = i >> 7, n = i & 127;
    float w0 = W1[(size_t)(2 * k2) * F_HID + n];
    float w1 = W1[(size_t)(2 * k2 + 1) * F_HID + n];
    __half2 h = __floats2half2_rn(w0, w1);
    g_w1h[i] = *(uint32_t*)&h;
}

// ============================================================================
// GEMM1 (mma.sync fp16, 2-term split): g_m1[N,128] = X[N,512] @ W1[512,128]
// Block 128x128, BK=32, 8 warps (4m x 2n), software-pipelined global loads.
// D = Ahi*Bh + Alo*Bh  (A split covers X to 2^-22; error = W1 fp16 rounding)
// ============================================================================
#define A_STRIDE 36
#define B_STRIDE 36

__global__ __launch_bounds__(256) void gemm1_mma(const float* __restrict__ X) {
    __shared__ __align__(16) unsigned short Ahi[128 * A_STRIDE];
    __shared__ __align__(16) unsigned short Alo[128 * A_STRIDE];
    __shared__ __align__(16) unsigned short Bh[128 * B_STRIDE];

    int tid = threadIdx.x;
    int wid = tid >> 5, lane = tid & 31;
    int warp_m = wid >> 1;
    int warp_n = wid & 1;
    int g = lane >> 2, tg = lane & 3;
    int mBase = blockIdx.x * 128;

    // A-tile addressing: thread loads 4 float4s (rows tid>>3 + 32*i)
    int aRow = tid >> 3, aK4 = tid & 7;
    bool aValid[4];
    const float* aPtr[4];
    #pragma unroll
    for (int i = 0; i < 4; i++) {
        int row = aRow + 32 * i;
        int grow = mBase + row;
        aValid[i] = grow < N_NODES;
        aPtr[i] = X + (size_t)(aValid[i] ? grow : 0) * F_IN + aK4 * 4;
    }
    // B-tile addressing: thread loads 8 uint32 pairs
    int bN = tid & 127, bK2 = tid >> 7;

    float acc[2][8][4];
    #pragma unroll
    for (int mt = 0; mt < 2; mt++)
        #pragma unroll
        for (int nt = 0; nt < 8; nt++)
            #pragma unroll
            for (int i = 0; i < 4; i++) acc[mt][nt][i] = 0.f;

    // --- prologue: load stage 0 into regs ---
    float4 aReg[4];
    uint32_t bReg[8];
    #pragma unroll
    for (int i = 0; i < 4; i++)
        aReg[i] = aValid[i] ? *(const float4*)(aPtr[i])
                            : make_float4(0.f, 0.f, 0.f, 0.f);
    #pragma unroll
    for (int i = 0; i < 8; i++)
        bReg[i] = g_w1h[(bK2 + 2 * i) * 128 + bN];

    for (int stage = 0; stage < 16; stage++) {
        // --- store regs -> smem (with A split) ---
        #pragma unroll
        for (int i = 0; i < 4; i++) {
            uint32_t h0, l0, h1, l1;
            split2h(aReg[i].x, aReg[i].y, h0, l0);
            split2h(aReg[i].z, aReg[i].w, h1, l1);
            int si = (aRow + 32 * i) * A_STRIDE + aK4 * 4;
            *(uint2*)&Ahi[si] = make_uint2(h0, h1);
            *(uint2*)&Alo[si] = make_uint2(l0, l1);
        }
        #pragma unroll
        for (int i = 0; i < 8; i++) {
            int si = bN * B_STRIDE + 2 * (bK2 + 2 * i);
            *(uint32_t*)&Bh[si] = bReg[i];
        }
        __syncthreads();

        // --- prefetch next stage ---
        if (stage < 15) {
            int kBase = (stage + 1) * 32;
            #pragma unroll
            for (int i = 0; i < 4; i++)
                aReg[i] = aValid[i] ? *(const float4*)(aPtr[i] + kBase)
                                    : make_float4(0.f, 0.f, 0.f, 0.f);
            #pragma unroll
            for (int i = 0; i < 8; i++)
                bReg[i] = g_w1h[(kBase / 2 + bK2 + 2 * i) * 128 + bN];
        }

        // --- compute from smem ---
        #pragma unroll
        for (int ks = 0; ks < 2; ks++) {
            int kk = ks * 16;
            uint32_t ah[2][4], al[2][4];
            #pragma unroll
            for (int mt = 0; mt < 2; mt++) {
                int base = (warp_m * 32 + mt * 16 + g) * A_STRIDE + kk + 2 * tg;
                ah[mt][0] = *(uint32_t*)&Ahi[base];
                ah[mt][1] = *(uint32_t*)&Ahi[base + 8 * A_STRIDE];
                ah[mt][2] = *(uint32_t*)&Ahi[base + 8];
                ah[mt][3] = *(uint32_t*)&Ahi[base + 8 * A_STRIDE + 8];
                al[mt][0] = *(uint32_t*)&Alo[base];
                al[mt][1] = *(uint32_t*)&Alo[base + 8 * A_STRIDE];
                al[mt][2] = *(uint32_t*)&Alo[base + 8];
                al[mt][3] = *(uint32_t*)&Alo[base + 8 * A_STRIDE + 8];
            }
            #pragma unroll
            for (int nt = 0; nt < 8; nt++) {
                int bbase = (warp_n * 64 + nt * 8 + g) * B_STRIDE + kk + 2 * tg;
                uint32_t b0 = *(uint32_t*)&Bh[bbase];
                uint32_t b1 = *(uint32_t*)&Bh[bbase + 8];
                #pragma unroll
                for (int mt = 0; mt < 2; mt++) {
                    mma16816h(acc[mt][nt], ah[mt], b0, b1);
                    mma16816h(acc[mt][nt], al[mt], b0, b1);
                }
            }
        }
        __syncthreads();
    }

    #pragma unroll
    for (int mt = 0; mt < 2; mt++) {
        int r0 = mBase + warp_m * 32 + mt * 16 + g;
        int r1 = r0 + 8;
        #pragma unroll
        for (int nt = 0; nt < 8; nt++) {
            int col = warp_n * 64 + nt * 8 + 2 * tg;
            if (r0 < N_NODES)
                *(float2*)(g_m1 + (size_t)r0 * F_HID + col) =
                    make_float2(acc[mt][nt][0], acc[mt][nt][1]);
            if (r1 < N_NODES)
                *(float2*)(g_m1 + (size_t)r1 * F_HID + col) =
                    make_float2(acc[mt][nt][2], acc[mt][nt][3]);
        }
    }
}

// ============================================================================
// CSR binning: histogram -> exclusive scan -> placement
// ============================================================================
__global__ __launch_bounds__(256) void bin_count(const int* __restrict__ ei) {
    int e = blockIdx.x * 256 + threadIdx.x;
    if (e < E_EDGES) atomicAdd(&g_deg[ei[E_EDGES + e]], 1);
}

__global__ __launch_bounds__(256) void scanA() {
    __shared__ int wsum[8];
    int t = threadIdx.x;
    int base = blockIdx.x * 1024 + t * 4;
    int v[4];
    #pragma unroll
    for (int i = 0; i < 4; i++)
        v[i] = (base + i < N_NODES) ? g_deg[base + i] : 0;
    int s = v[0] + v[1] + v[2] + v[3];
    int lane = t & 31, w = t >> 5;
    int inc = s;
    #pragma unroll
    for (int o = 1; o < 32; o <<= 1) {
        int n = __shfl_up_sync(0xFFFFFFFFu, inc, o);
        if (lane >= o) inc += n;
    }
    if (lane == 31) wsum[w] = inc;
    __syncthreads();
    if (t == 0) {
        int run = 0;
        #pragma unroll
        for (int i = 0; i < 8; i++) { int x = wsum[i]; wsum[i] = run; run += x; }
        g_bsum[blockIdx.x] = run;
    }
    __syncthreads();
    int excl = inc - s + wsum[w];
    int o0 = excl, o1 = o0 + v[0], o2 = o1 + v[1], o3 = o2 + v[2];
    if (base + 0 < N_NODES) g_off[base + 0] = o0;
    if (base + 1 < N_NODES) g_off[base + 1] = o1;
    if (base + 2 < N_NODES) g_off[base + 2] = o2;
    if (base + 3 < N_NODES) g_off[base + 3] = o3;
}

__global__ __launch_bounds__(128) void scanB(int nb) {
    __shared__ int ws[4];
    int t = threadIdx.x;
    int v = (t < nb) ? g_bsum[t] : 0;
    int lane = t & 31, w = t >> 5;
    int inc = v;
    #pragma unroll
    for (int o = 1; o < 32; o <<= 1) {
        int n = __shfl_up_sync(0xFFFFFFFFu, inc, o);
        if (lane >= o) inc += n;
    }
    if (lane == 31) ws[w] = inc;
    __syncthreads();
    if (t == 0) {
        int run = 0;
        #pragma unroll
        for (int i = 0; i < 4; i++) { int x = ws[i]; ws[i] = run; run += x; }
    }
    __syncthreads();
    if (t < nb) g_bscan[t] = inc - v + ws[w];
}

__global__ __launch_bounds__(256) void scanC() {
    int add = g_bscan[blockIdx.x];
    int base = blockIdx.x * 1024 + threadIdx.x;
    #pragma unroll
    for (int i = 0; i < 4; i++) {
        int idx = base + i * 256;
        if (idx < N_NODES) {
            int val = g_off[idx] + add;
            g_off[idx] = val;
            g_cur[idx] = val;
        }
    }
}

__global__ __launch_bounds__(256) void bin_fill(const int* __restrict__ ei,
                                                const float* __restrict__ ew) {
    int e = blockIdx.x * 256 + threadIdx.x;
    if (e >= E_EDGES) return;
    int src = ei[e];
    int dst = ei[E_EDGES + e];
    int pos = atomicAdd(&g_cur[dst], 1);
    g_esrc[pos] = src;
    g_ewp[pos] = ew[e];
}

// ============================================================================
// Agg1 (dst-driven, fused b1+relu), 4-deep unroll for MLP
// ============================================================================
__global__ __launch_bounds__(256) void agg1_kernel(const float* __restrict__ b1) {
    int wv = blockIdx.x * 8 + (threadIdx.x >> 5);
    int lane = threadIdx.x & 31;
    if (wv >= N_NODES) return;
    int beg = g_off[wv];
    int end = (wv == N_NODES - 1) ? E_EDGES : g_off[wv + 1];

    float4 a0 = make_float4(0.f, 0.f, 0.f, 0.f);
    float4 a1 = make_float4(0.f, 0.f, 0.f, 0.f);
    float4 a2 = make_float4(0.f, 0.f, 0.f, 0.f);
    float4 a3 = make_float4(0.f, 0.f, 0.f, 0.f);
    int j = beg;
    for (; j + 4 <= end; j += 4) {
        int s0 = g_esrc[j], s1 = g_esrc[j + 1], s2 = g_esrc[j + 2], s3 = g_esrc[j + 3];
        float w0 = g_ewp[j], w1 = g_ewp[j + 1], w2 = g_ewp[j + 2], w3 = g_ewp[j + 3];
        float4 m0 = ((const float4*)(g_m1 + (size_t)s0 * F_HID))[lane];
        float4 m1v = ((const float4*)(g_m1 + (size_t)s1 * F_HID))[lane];
        float4 m2v = ((const float4*)(g_m1 + (size_t)s2 * F_HID))[lane];
        float4 m3v = ((const float4*)(g_m1 + (size_t)s3 * F_HID))[lane];
        a0.x += m0.x * w0; a0.y += m0.y * w0; a0.z += m0.z * w0; a0.w += m0.w * w0;
        a1.x += m1v.x * w1; a1.y += m1v.y * w1; a1.z += m1v.z * w1; a1.w += m1v.w * w1;
        a2.x += m2v.x * w2; a2.y += m2v.y * w2; a2.z += m2v.z * w2; a2.w += m2v.w * w2;
        a3.x += m3v.x * w3; a3.y += m3v.y * w3; a3.z += m3v.z * w3; a3.w += m3v.w * w3;
    }
    for (; j < end; j++) {
        int s0 = g_esrc[j];
        float w0 = g_ewp[j];
        float4 m0 = ((const float4*)(g_m1 + (size_t)s0 * F_HID))[lane];
        a0.x += m0.x * w0; a0.y += m0.y * w0; a0.z += m0.z * w0; a0.w += m0.w * w0;
    }
    float4 bb = ((const float4*)b1)[lane];
    float4 r;
    r.x = fmaxf(a0.x + a1.x + a2.x + a3.x + bb.x, 0.f);
    r.y = fmaxf(a0.y + a1.y + a2.y + a3.y + bb.y, 0.f);
    r.z = fmaxf(a0.z + a1.z + a2.z + a3.z + bb.z, 0.f);
    r.w = fmaxf(a0.w + a1.w + a2.w + a3.w + bb.w, 0.f);
    ((float4*)(g_agg1 + (size_t)wv * F_HID))[lane] = r;
}

// ============================================================================
// GEMM2: g_m2[N,40] = agg1 @ W2[128,40]
// ============================================================================
#define G2_SMEM ((5120 + 128 * 132) * 4)

__global__ __launch_bounds__(256) void gemm2_kernel(const float* __restrict__ W2) {
    extern __shared__ float dsm[];
    float* W2s = dsm;                 // [128][40]
    float* hs  = dsm + 5120;          // [128][132]

    int tid = threadIdx.x;
    for (int i = tid; i < F_HID * F_OUT; i += 256) W2s[i] = W2[i];
    __syncthreads();

    int rowBase = blockIdx.x * 128;
    for (int idx = tid; idx < 128 * 32; idx += 256) {
        int r = idx >> 5, c4 = idx & 31;
        int row = rowBase + r;
        float4 v = make_float4(0.f, 0.f, 0.f, 0.f);
        if (row < N_NODES)
            v = ((const float4*)(g_agg1 + (size_t)row * F_HID))[c4];
        *(float4*)&hs[r * 132 + c4 * 4] = v;
    }
    __syncthreads();

    int r = tid >> 1;
    int half = tid & 1;
    const float* hrow = &hs[r * 132 + half * 64];
    const float* w2h = W2s + half * 64 * F_OUT;
    float acc[40];
    #pragma unroll
    for (int c = 0; c < 40; c++) acc[c] = 0.f;
    #pragma unroll 4
    for (int k = 0; k < 64; k++) {
        float hv = hrow[k];
        const float4* wr = (const float4*)(w2h + k * F_OUT);
        #pragma unroll
        for (int c = 0; c < 10; c++) {
            float4 w = wr[c];
            acc[c * 4 + 0] += hv * w.x;
            acc[c * 4 + 1] += hv * w.y;
            acc[c * 4 + 2] += hv * w.z;
            acc[c * 4 + 3] += hv * w.w;
        }
    }
    __syncthreads();
    float* red = hs;                  // [128][41]
    if (half) {
        #pragma unroll
        for (int c = 0; c < 40; c++) red[r * 41 + c] = acc[c];
    }
    __syncthreads();
    if (!half) {
        #pragma unroll
        for (int c = 0; c < 40; c++) red[r * 41 + c] += acc[c];
    }
    __syncthreads();

    int nValid = min(128, N_NODES - rowBase);
    for (int idx = tid; idx < 128 * 10; idx += 256) {
        int rr = idx / 10, c4 = idx % 10;
        if (rr < nValid) {
            float4 v = make_float4(red[rr * 41 + c4 * 4 + 0], red[rr * 41 + c4 * 4 + 1],
                                   red[rr * 41 + c4 * 4 + 2], red[rr * 41 + c4 * 4 + 3]);
            *(float4*)(g_m2 + (size_t)(rowBase + rr) * F_OUT + c4 * 4) = v;
        }
    }
}

// ============================================================================
// Agg2 + b2 + log_softmax fused (dst-driven), 4-deep unroll
// ============================================================================
__global__ __launch_bounds__(256) void agg2_ls_kernel(const float* __restrict__ b2,
                                                      float* __restrict__ out) {
    int wv = blockIdx.x * 8 + (threadIdx.x >> 5);
    int lane = threadIdx.x & 31;
    if (wv >= N_NODES) return;
    int beg = g_off[wv];
    int end = (wv == N_NODES - 1) ? E_EDGES : g_off[wv + 1];
    bool act = lane < 10;

    float4 a0 = make_float4(0.f, 0.f, 0.f, 0.f);
    float4 a1 = make_float4(0.f, 0.f, 0.f, 0.f);
    float4 a2 = make_float4(0.f, 0.f, 0.f, 0.f);
    float4 a3 = make_float4(0.f, 0.f, 0.f, 0.f);
    int j = beg;
    for (; j + 4 <= end; j += 4) {
        int s0 = g_esrc[j], s1 = g_esrc[j + 1], s2 = g_esrc[j + 2], s3 = g_esrc[j + 3];
        float w0 = g_ewp[j], w1 = g_ewp[j + 1], w2 = g_ewp[j + 2], w3 = g_ewp[j + 3];
        if (act) {
            float4 m0 = ((const float4*)(g_m2 + (size_t)s0 * F_OUT))[lane];
            float4 m1v = ((const float4*)(g_m2 + (size_t)s1 * F_OUT))[lane];
            float4 m2v = ((const float4*)(g_m2 + (size_t)s2 * F_OUT))[lane];
            float4 m3v = ((const float4*)(g_m2 + (size_t)s3 * F_OUT))[lane];
            a0.x += m0.x * w0; a0.y += m0.y * w0; a0.z += m0.z * w0; a0.w += m0.w * w0;
            a1.x += m1v.x * w1; a1.y += m1v.y * w1; a1.z += m1v.z * w1; a1.w += m1v.w * w1;
            a2.x += m2v.x * w2; a2.y += m2v.y * w2; a2.z += m2v.z * w2; a2.w += m2v.w * w2;
            a3.x += m3v.x * w3; a3.y += m3v.y * w3; a3.z += m3v.z * w3; a3.w += m3v.w * w3;
        }
    }
    for (; j < end; j++) {
        int s0 = g_esrc[j];
        float w0 = g_ewp[j];
        if (act) {
            float4 m0 = ((const float4*)(g_m2 + (size_t)s0 * F_OUT))[lane];
            a0.x += m0.x * w0; a0.y += m0.y * w0; a0.z += m0.z * w0; a0.w += m0.w * w0;
        }
    }
    float4 x = make_float4(a0.x + a1.x + a2.x + a3.x, a0.y + a1.y + a2.y + a3.y,
                           a0.z + a1.z + a2.z + a3.z, a0.w + a1.w + a2.w + a3.w);
    if (act) {
        float4 bb = ((const float4*)b2)[lane];
        x.x += bb.x; x.y += bb.y; x.z += bb.z; x.w += bb.w;
    }

    float m = act ? fmaxf(fmaxf(x.x, x.y), fmaxf(x.z, x.w)) : -1e30f;
    #pragma unroll
    for (int o = 16; o; o >>= 1) m = fmaxf(m, __shfl_xor_sync(0xFFFFFFFFu, m, o));

    float s = act ? (__expf(x.x - m) + __expf(x.y - m) +
                     __expf(x.z - m) + __expf(x.w - m)) : 0.f;
    #pragma unroll
    for (int o = 16; o; o >>= 1) s += __shfl_xor_sync(0xFFFFFFFFu, s, o);

    float lse = m + __logf(s);
    if (act) {
        x.x -= lse; x.y -= lse; x.z -= lse; x.w -= lse;
        ((float4*)(out + (size_t)wv * F_OUT))[lane] = x;
    }
}

// ============================================================================
extern "C" void kernel_launch(void* const* d_in, const int* in_sizes, int n_in,
                              void* d_out, int out_size) {
    const float* X   = (const float*)d_in[0];        // [100000,512]
    const int*   EI  = (const int*)d_in[1];          // [2,1600000] int32
    const float* EW  = (const float*)d_in[2];        // [1600000]
    const float* W1  = (const float*)d_in[3];        // [512,128]
    const float* B1  = (const float*)d_in[4];        // [128]
    const float* W2  = (const float*)d_in[5];        // [128,40]
    const float* B2  = (const float*)d_in[6];        // [40]
    float*       OUT = (float*)d_out;                // [100000,40]

    cudaFuncSetAttribute(gemm2_kernel, cudaFuncAttributeMaxDynamicSharedMemorySize,
                         G2_SMEM);

    const int NB_SCAN = (N_NODES + 1023) / 1024;     // 98
    const int EB = E_EDGES / 256;                    // 6250 (exact)

    // 0. zero degree histogram + round W1 to fp16
    void* degPtr = nullptr;
    cudaGetSymbolAddress(&degPtr, g_deg);
    cudaMemsetAsync(degPtr, 0, N_NODES * sizeof(int));
    prep_w1<<<128, 256>>>(W1);

    // 1. GEMM1 (tensor mma fp16 2-term split): m1 = X @ W1
    gemm1_mma<<<(N_NODES + 127) / 128, 256>>>(X);

    // 2. CSR binning (shared by both layers)
    bin_count<<<EB, 256>>>(EI);
    scanA<<<NB_SCAN, 256>>>();
    scanB<<<1, 128>>>(NB_SCAN);
    scanC<<<NB_SCAN, 256>>>();
    bin_fill<<<EB, 256>>>(EI, EW);

    // 3. Agg1 (fused b1 + relu): agg1 = relu(S(m1) + b1)
    agg1_kernel<<<(N_NODES + 7) / 8, 256>>>(B1);

    // 4. GEMM2: m2 = agg1 @ W2
    gemm2_kernel<<<(N_NODES + 127) / 128, 256, G2_SMEM>>>(W2);

    // 5. Agg2 + b2 + log_softmax fused, writes d_out
    agg2_ls_kernel<<<(N_NODES + 7) / 8, 256>>>(B2, OUT);
}

// round 12
// speedup vs baseline: 1.8813x; 1.0788x over previous
#include <cuda_runtime.h>
#include <cuda_fp16.h>
#include <cstdint>

#define N_NODES 100000
#define E_EDGES 1600000
#define F_IN    512
#define F_HID   128
#define F_OUT   40

// Scratch (allocation-free rule: __device__ globals)
__device__ float g_m1[(size_t)N_NODES * F_HID];    // X @ W1
__device__ float g_agg1[(size_t)N_NODES * F_HID];  // relu(scatter-sum + b1)
__device__ float g_m2[(size_t)N_NODES * F_OUT];    // h @ W2

// W1 fp16, pair-packed: [k2][n] uint32 = (fp16(W[2k2][n]), fp16(W[2k2+1][n]))
__device__ uint32_t g_w1h[256 * 128];

// CSR binning scratch (rebuilt every launch)
__device__ int   g_deg[N_NODES];
__device__ int   g_off[N_NODES];
__device__ int   g_cur[N_NODES];
__device__ int   g_bsum[128];
__device__ int   g_bscan[128];
__device__ int   g_esrc[E_EDGES];
__device__ float g_ewp[E_EDGES];

// ============================================================================
// helpers
// ============================================================================
__device__ __forceinline__ void mma16816h(float* d, const uint32_t* a,
                                          uint32_t b0, uint32_t b1) {
    asm volatile(
        "mma.sync.aligned.m16n8k16.row.col.f32.f16.f16.f32 "
        "{%0,%1,%2,%3}, {%4,%5,%6,%7}, {%8,%9}, {%0,%1,%2,%3};"
        : "+f"(d[0]), "+f"(d[1]), "+f"(d[2]), "+f"(d[3])
        : "r"(a[0]), "r"(a[1]), "r"(a[2]), "r"(a[3]), "r"(b0), "r"(b1));
}

__device__ __forceinline__ void ldmx4(uint32_t* r, uint32_t addr) {
    asm volatile(
        "ldmatrix.sync.aligned.m8n8.x4.shared.b16 {%0,%1,%2,%3}, [%4];"
        : "=r"(r[0]), "=r"(r[1]), "=r"(r[2]), "=r"(r[3]) : "r"(addr));
}

// fp16 hi/lo split of a pair of floats (packed half2 as uint32)
__device__ __forceinline__ void split2h(float x, float y,
                                        uint32_t& hi, uint32_t& lo) {
    __half2 h = __floats2half2_rn(x, y);
    float hx = __half2float(__low2half(h)), hy = __half2float(__high2half(h));
    __half2 l = __floats2half2_rn(x - hx, y - hy);
    hi = *(uint32_t*)&h;
    lo = *(uint32_t*)&l;
}

// ============================================================================
// prep_w1: round W1 once to pair-packed fp16  (32768 elements)
// ============================================================================
__global__ __launch_bounds__(256) void prep_w1(const float* __restrict__ W1) {
    int i = blockIdx.x * 256 + threadIdx.x;   // i = k2*128 + n
    int k2 = i >> 7, n = i & 127;
    float w0 = W1[(size_t)(2 * k2) * F_HID + n];
    float w1 = W1[(size_t)(2 * k2 + 1) * F_HID + n];
    __half2 h = __floats2half2_rn(w0, w1);
    g_w1h[i] = *(uint32_t*)&h;
}

// ============================================================================
// GEMM1 (mma.sync fp16, 2-term split): g_m1[N,128] = X[N,512] @ W1[512,128]
// Block 128x128, BK=32, 8 warps (4m x 2n), sw-pipelined LDG, ldmatrix frags.
// D = Ahi*Bh + Alo*Bh
// ============================================================================
#define A_STRIDE 40   // 80B rows -> ldmatrix 8-row groups hit distinct banks
#define B_STRIDE 40

__global__ __launch_bounds__(256) void gemm1_mma(const float* __restrict__ X) {
    __shared__ __align__(16) unsigned short Ahi[128 * A_STRIDE];
    __shared__ __align__(16) unsigned short Alo[128 * A_STRIDE];
    __shared__ __align__(16) unsigned short Bh[128 * B_STRIDE];

    int tid = threadIdx.x;
    int wid = tid >> 5, lane = tid & 31;
    int warp_m = wid >> 1;
    int warp_n = wid & 1;
    int mBase = blockIdx.x * 128;

    uint32_t sAhi = (uint32_t)__cvta_generic_to_shared(Ahi);
    uint32_t sAlo = (uint32_t)__cvta_generic_to_shared(Alo);
    uint32_t sBh  = (uint32_t)__cvta_generic_to_shared(Bh);

    // A-tile addressing: thread loads 4 float4s (rows tid>>3 + 32*i)
    int aRow = tid >> 3, aK4 = tid & 7;
    bool aValid[4];
    const float* aPtr[4];
    #pragma unroll
    for (int i = 0; i < 4; i++) {
        int row = aRow + 32 * i;
        int grow = mBase + row;
        aValid[i] = grow < N_NODES;
        aPtr[i] = X + (size_t)(aValid[i] ? grow : 0) * F_IN + aK4 * 4;
    }
    // B-tile addressing: thread loads 8 uint32 pairs
    int bN = tid & 127, bK2 = tid >> 7;

    // ldmatrix per-thread source rows
    int g4 = lane >> 3, r8 = lane & 7;

    float acc[2][8][4];
    #pragma unroll
    for (int mt = 0; mt < 2; mt++)
        #pragma unroll
        for (int nt = 0; nt < 8; nt++)
            #pragma unroll
            for (int i = 0; i < 4; i++) acc[mt][nt][i] = 0.f;

    // --- prologue: load stage 0 into regs ---
    float4 aReg[4];
    uint32_t bReg[8];
    #pragma unroll
    for (int i = 0; i < 4; i++)
        aReg[i] = aValid[i] ? *(const float4*)(aPtr[i])
                            : make_float4(0.f, 0.f, 0.f, 0.f);
    #pragma unroll
    for (int i = 0; i < 8; i++)
        bReg[i] = g_w1h[(bK2 + 2 * i) * 128 + bN];

    for (int stage = 0; stage < 16; stage++) {
        // --- store regs -> smem (with A split) ---
        #pragma unroll
        for (int i = 0; i < 4; i++) {
            uint32_t h0, l0, h1, l1;
            split2h(aReg[i].x, aReg[i].y, h0, l0);
            split2h(aReg[i].z, aReg[i].w, h1, l1);
            int si = (aRow + 32 * i) * A_STRIDE + aK4 * 4;
            *(uint2*)&Ahi[si] = make_uint2(h0, h1);
            *(uint2*)&Alo[si] = make_uint2(l0, l1);
        }
        #pragma unroll
        for (int i = 0; i < 8; i++) {
            int si = bN * B_STRIDE + 2 * (bK2 + 2 * i);
            *(uint32_t*)&Bh[si] = bReg[i];
        }
        __syncthreads();

        // --- prefetch next stage ---
        if (stage < 15) {
            int kBase = (stage + 1) * 32;
            #pragma unroll
            for (int i = 0; i < 4; i++)
                aReg[i] = aValid[i] ? *(const float4*)(aPtr[i] + kBase)
                                    : make_float4(0.f, 0.f, 0.f, 0.f);
            #pragma unroll
            for (int i = 0; i < 8; i++)
                bReg[i] = g_w1h[(kBase / 2 + bK2 + 2 * i) * 128 + bN];
        }

        // --- compute from smem via ldmatrix ---
        #pragma unroll
        for (int ks = 0; ks < 2; ks++) {
            int kk = ks * 16;
            // A fragments: tile order T0(r0-7,klo) T1(r8-15,klo) T2(r0-7,khi) T3(r8-15,khi)
            int aSrcRow = (g4 & 1) * 8 + r8;
            int aSrcCol = kk + (g4 >> 1) * 8;
            uint32_t ah[2][4], al[2][4];
            #pragma unroll
            for (int mt = 0; mt < 2; mt++) {
                uint32_t off = ((warp_m * 32 + mt * 16 + aSrcRow) * A_STRIDE + aSrcCol) * 2;
                ldmx4(ah[mt], sAhi + off);
                ldmx4(al[mt], sAlo + off);
            }
            // B fragments: per nt-pair, tiles (nt,klo)(nt,khi)(nt+1,klo)(nt+1,khi)
            int bSrcN = (g4 >> 1) * 8 + r8;
            int bSrcK = kk + (g4 & 1) * 8;
            #pragma unroll
            for (int nt2 = 0; nt2 < 4; nt2++) {
                uint32_t b[4];
                uint32_t off = ((warp_n * 64 + nt2 * 16 + bSrcN) * B_STRIDE + bSrcK) * 2;
                ldmx4(b, sBh + off);
                #pragma unroll
                for (int mt = 0; mt < 2; mt++) {
                    mma16816h(acc[mt][2 * nt2 + 0], ah[mt], b[0], b[1]);
                    mma16816h(acc[mt][2 * nt2 + 0], al[mt], b[0], b[1]);
                    mma16816h(acc[mt][2 * nt2 + 1], ah[mt], b[2], b[3]);
                    mma16816h(acc[mt][2 * nt2 + 1], al[mt], b[2], b[3]);
                }
            }
        }
        __syncthreads();
    }

    int g = lane >> 2, tg = lane & 3;
    #pragma unroll
    for (int mt = 0; mt < 2; mt++) {
        int r0 = mBase + warp_m * 32 + mt * 16 + g;
        int r1 = r0 + 8;
        #pragma unroll
        for (int nt = 0; nt < 8; nt++) {
            int col = warp_n * 64 + nt * 8 + 2 * tg;
            if (r0 < N_NODES)
                *(float2*)(g_m1 + (size_t)r0 * F_HID + col) =
                    make_float2(acc[mt][nt][0], acc[mt][nt][1]);
            if (r1 < N_NODES)
                *(float2*)(g_m1 + (size_t)r1 * F_HID + col) =
                    make_float2(acc[mt][nt][2], acc[mt][nt][3]);
        }
    }
}

// ============================================================================
// CSR binning: histogram -> exclusive scan -> placement
// ============================================================================
__global__ __launch_bounds__(256) void bin_count(const int* __restrict__ ei) {
    int e = blockIdx.x * 256 + threadIdx.x;
    if (e < E_EDGES) atomicAdd(&g_deg[ei[E_EDGES + e]], 1);
}

__global__ __launch_bounds__(256) void scanA() {
    __shared__ int wsum[8];
    int t = threadIdx.x;
    int base = blockIdx.x * 1024 + t * 4;
    int v[4];
    #pragma unroll
    for (int i = 0; i < 4; i++)
        v[i] = (base + i < N_NODES) ? g_deg[base + i] : 0;
    int s = v[0] + v[1] + v[2] + v[3];
    int lane = t & 31, w = t >> 5;
    int inc = s;
    #pragma unroll
    for (int o = 1; o < 32; o <<= 1) {
        int n = __shfl_up_sync(0xFFFFFFFFu, inc, o);
        if (lane >= o) inc += n;
    }
    if (lane == 31) wsum[w] = inc;
    __syncthreads();
    if (t == 0) {
        int run = 0;
        #pragma unroll
        for (int i = 0; i < 8; i++) { int x = wsum[i]; wsum[i] = run; run += x; }
        g_bsum[blockIdx.x] = run;
    }
    __syncthreads();
    int excl = inc - s + wsum[w];
    int o0 = excl, o1 = o0 + v[0], o2 = o1 + v[1], o3 = o2 + v[2];
    if (base + 0 < N_NODES) g_off[base + 0] = o0;
    if (base + 1 < N_NODES) g_off[base + 1] = o1;
    if (base + 2 < N_NODES) g_off[base + 2] = o2;
    if (base + 3 < N_NODES) g_off[base + 3] = o3;
}

__global__ __launch_bounds__(128) void scanB(int nb) {
    __shared__ int ws[4];
    int t = threadIdx.x;
    int v = (t < nb) ? g_bsum[t] : 0;
    int lane = t & 31, w = t >> 5;
    int inc = v;
    #pragma unroll
    for (int o = 1; o < 32; o <<= 1) {
        int n = __shfl_up_sync(0xFFFFFFFFu, inc, o);
        if (lane >= o) inc += n;
    }
    if (lane == 31) ws[w] = inc;
    __syncthreads();
    if (t == 0) {
        int run = 0;
        #pragma unroll
        for (int i = 0; i < 4; i++) { int x = ws[i]; ws[i] = run; run += x; }
    }
    __syncthreads();
    if (t < nb) g_bscan[t] = inc - v + ws[w];
}

__global__ __launch_bounds__(256) void scanC() {
    int add = g_bscan[blockIdx.x];
    int base = blockIdx.x * 1024 + threadIdx.x;
    #pragma unroll
    for (int i = 0; i < 4; i++) {
        int idx = base + i * 256;
        if (idx < N_NODES) {
            int val = g_off[idx] + add;
            g_off[idx] = val;
            g_cur[idx] = val;
        }
    }
}

__global__ __launch_bounds__(256) void bin_fill(const int* __restrict__ ei,
                                                const float* __restrict__ ew) {
    int e = blockIdx.x * 256 + threadIdx.x;
    if (e >= E_EDGES) return;
    int src = ei[e];
    int dst = ei[E_EDGES + e];
    int pos = atomicAdd(&g_cur[dst], 1);
    g_esrc[pos] = src;
    g_ewp[pos] = ew[e];
}

// ============================================================================
// Agg1 (dst-driven, fused b1+relu), 4-deep unroll for MLP
// ============================================================================
__global__ __launch_bounds__(256) void agg1_kernel(const float* __restrict__ b1) {
    int wv = blockIdx.x * 8 + (threadIdx.x >> 5);
    int lane = threadIdx.x & 31;
    if (wv >= N_NODES) return;
    int beg = g_off[wv];
    int end = (wv == N_NODES - 1) ? E_EDGES : g_off[wv + 1];

    float4 a0 = make_float4(0.f, 0.f, 0.f, 0.f);
    float4 a1 = make_float4(0.f, 0.f, 0.f, 0.f);
    float4 a2 = make_float4(0.f, 0.f, 0.f, 0.f);
    float4 a3 = make_float4(0.f, 0.f, 0.f, 0.f);
    int j = beg;
    for (; j + 4 <= end; j += 4) {
        int s0 = g_esrc[j], s1 = g_esrc[j + 1], s2 = g_esrc[j + 2], s3 = g_esrc[j + 3];
        float w0 = g_ewp[j], w1 = g_ewp[j + 1], w2 = g_ewp[j + 2], w3 = g_ewp[j + 3];
        float4 m0 = ((const float4*)(g_m1 + (size_t)s0 * F_HID))[lane];
        float4 m1v = ((const float4*)(g_m1 + (size_t)s1 * F_HID))[lane];
        float4 m2v = ((const float4*)(g_m1 + (size_t)s2 * F_HID))[lane];
        float4 m3v = ((const float4*)(g_m1 + (size_t)s3 * F_HID))[lane];
        a0.x += m0.x * w0; a0.y += m0.y * w0; a0.z += m0.z * w0; a0.w += m0.w * w0;
        a1.x += m1v.x * w1; a1.y += m1v.y * w1; a1.z += m1v.z * w1; a1.w += m1v.w * w1;
        a2.x += m2v.x * w2; a2.y += m2v.y * w2; a2.z += m2v.z * w2; a2.w += m2v.w * w2;
        a3.x += m3v.x * w3; a3.y += m3v.y * w3; a3.z += m3v.z * w3; a3.w += m3v.w * w3;
    }
    for (; j < end; j++) {
        int s0 = g_esrc[j];
        float w0 = g_ewp[j];
        float4 m0 = ((const float4*)(g_m1 + (size_t)s0 * F_HID))[lane];
        a0.x += m0.x * w0; a0.y += m0.y * w0; a0.z += m0.z * w0; a0.w += m0.w * w0;
    }
    float4 bb = ((const float4*)b1)[lane];
    float4 r;
    r.x = fmaxf(a0.x + a1.x + a2.x + a3.x + bb.x, 0.f);
    r.y = fmaxf(a0.y + a1.y + a2.y + a3.y + bb.y, 0.f);
    r.z = fmaxf(a0.z + a1.z + a2.z + a3.z + bb.z, 0.f);
    r.w = fmaxf(a0.w + a1.w + a2.w + a3.w + bb.w, 0.f);
    ((float4*)(g_agg1 + (size_t)wv * F_HID))[lane] = r;
}

// ============================================================================
// GEMM2: g_m2[N,40] = agg1 @ W2[128,40]
// ============================================================================
#define G2_SMEM ((5120 + 128 * 132) * 4)

__global__ __launch_bounds__(256) void gemm2_kernel(const float* __restrict__ W2) {
    extern __shared__ float dsm[];
    float* W2s = dsm;                 // [128][40]
    float* hs  = dsm + 5120;          // [128][132]

    int tid = threadIdx.x;
    for (int i = tid; i < F_HID * F_OUT; i += 256) W2s[i] = W2[i];
    __syncthreads();

    int rowBase = blockIdx.x * 128;
    for (int idx = tid; idx < 128 * 32; idx += 256) {
        int r = idx >> 5, c4 = idx & 31;
        int row = rowBase + r;
        float4 v = make_float4(0.f, 0.f, 0.f, 0.f);
        if (row < N_NODES)
            v = ((const float4*)(g_agg1 + (size_t)row * F_HID))[c4];
        *(float4*)&hs[r * 132 + c4 * 4] = v;
    }
    __syncthreads();

    int r = tid >> 1;
    int half = tid & 1;
    const float* hrow = &hs[r * 132 + half * 64];
    const float* w2h = W2s + half * 64 * F_OUT;
    float acc[40];
    #pragma unroll
    for (int c = 0; c < 40; c++) acc[c] = 0.f;
    #pragma unroll 4
    for (int k = 0; k < 64; k++) {
        float hv = hrow[k];
        const float4* wr = (const float4*)(w2h + k * F_OUT);
        #pragma unroll
        for (int c = 0; c < 10; c++) {
            float4 w = wr[c];
            acc[c * 4 + 0] += hv * w.x;
            acc[c * 4 + 1] += hv * w.y;
            acc[c * 4 + 2] += hv * w.z;
            acc[c * 4 + 3] += hv * w.w;
        }
    }
    __syncthreads();
    float* red = hs;                  // [128][41]
    if (half) {
        #pragma unroll
        for (int c = 0; c < 40; c++) red[r * 41 + c] = acc[c];
    }
    __syncthreads();
    if (!half) {
        #pragma unroll
        for (int c = 0; c < 40; c++) red[r * 41 + c] += acc[c];
    }
    __syncthreads();

    int nValid = min(128, N_NODES - rowBase);
    for (int idx = tid; idx < 128 * 10; idx += 256) {
        int rr = idx / 10, c4 = idx % 10;
        if (rr < nValid) {
            float4 v = make_float4(red[rr * 41 + c4 * 4 + 0], red[rr * 41 + c4 * 4 + 1],
                                   red[rr * 41 + c4 * 4 + 2], red[rr * 41 + c4 * 4 + 3]);
            *(float4*)(g_m2 + (size_t)(rowBase + rr) * F_OUT + c4 * 4) = v;
        }
    }
}

// ============================================================================
// Agg2 + b2 + log_softmax fused (dst-driven), 4-deep unroll
// ============================================================================
__global__ __launch_bounds__(256) void agg2_ls_kernel(const float* __restrict__ b2,
                                                      float* __restrict__ out) {
    int wv = blockIdx.x * 8 + (threadIdx.x >> 5);
    int lane = threadIdx.x & 31;
    if (wv >= N_NODES) return;
    int beg = g_off[wv];
    int end = (wv == N_NODES - 1) ? E_EDGES : g_off[wv + 1];
    bool act = lane < 10;

    float4 a0 = make_float4(0.f, 0.f, 0.f, 0.f);
    float4 a1 = make_float4(0.f, 0.f, 0.f, 0.f);
    float4 a2 = make_float4(0.f, 0.f, 0.f, 0.f);
    float4 a3 = make_float4(0.f, 0.f, 0.f, 0.f);
    int j = beg;
    for (; j + 4 <= end; j += 4) {
        int s0 = g_esrc[j], s1 = g_esrc[j + 1], s2 = g_esrc[j + 2], s3 = g_esrc[j + 3];
        float w0 = g_ewp[j], w1 = g_ewp[j + 1], w2 = g_ewp[j + 2], w3 = g_ewp[j + 3];
        if (act) {
            float4 m0 = ((const float4*)(g_m2 + (size_t)s0 * F_OUT))[lane];
            float4 m1v = ((const float4*)(g_m2 + (size_t)s1 * F_OUT))[lane];
            float4 m2v = ((const float4*)(g_m2 + (size_t)s2 * F_OUT))[lane];
            float4 m3v = ((const float4*)(g_m2 + (size_t)s3 * F_OUT))[lane];
            a0.x += m0.x * w0; a0.y += m0.y * w0; a0.z += m0.z * w0; a0.w += m0.w * w0;
            a1.x += m1v.x * w1; a1.y += m1v.y * w1; a1.z += m1v.z * w1; a1.w += m1v.w * w1;
            a2.x += m2v.x * w2; a2.y += m2v.y * w2; a2.z += m2v.z * w2; a2.w += m2v.w * w2;
            a3.x += m3v.x * w3; a3.y += m3v.y * w3; a3.z += m3v.z * w3; a3.w += m3v.w * w3;
        }
    }
    for (; j < end; j++) {
        int s0 = g_esrc[j];
        float w0 = g_ewp[j];
        if (act) {
            float4 m0 = ((const float4*)(g_m2 + (size_t)s0 * F_OUT))[lane];
            a0.x += m0.x * w0; a0.y += m0.y * w0; a0.z += m0.z * w0; a0.w += m0.w * w0;
        }
    }
    float4 x = make_float4(a0.x + a1.x + a2.x + a3.x, a0.y + a1.y + a2.y + a3.y,
                           a0.z + a1.z + a2.z + a3.z, a0.w + a1.w + a2.w + a3.w);
    if (act) {
        float4 bb = ((const float4*)b2)[lane];
        x.x += bb.x; x.y += bb.y; x.z += bb.z; x.w += bb.w;
    }

    float m = act ? fmaxf(fmaxf(x.x, x.y), fmaxf(x.z, x.w)) : -1e30f;
    #pragma unroll
    for (int o = 16; o; o >>= 1) m = fmaxf(m, __shfl_xor_sync(0xFFFFFFFFu, m, o));

    float s = act ? (__expf(x.x - m) + __expf(x.y - m) +
                     __expf(x.z - m) + __expf(x.w - m)) : 0.f;
    #pragma unroll
    for (int o = 16; o; o >>= 1) s += __shfl_xor_sync(0xFFFFFFFFu, s, o);

    float lse = m + __logf(s);
    if (act) {
        x.x -= lse; x.y -= lse; x.z -= lse; x.w -= lse;
        ((float4*)(out + (size_t)wv * F_OUT))[lane] = x;
    }
}

// ============================================================================
extern "C" void kernel_launch(void* const* d_in, const int* in_sizes, int n_in,
                              void* d_out, int out_size) {
    const float* X   = (const float*)d_in[0];        // [100000,512]
    const int*   EI  = (const int*)d_in[1];          // [2,1600000] int32
    const float* EW  = (const float*)d_in[2];        // [1600000]
    const float* W1  = (const float*)d_in[3];        // [512,128]
    const float* B1  = (const float*)d_in[4];        // [128]
    const float* W2  = (const float*)d_in[5];        // [128,40]
    const float* B2  = (const float*)d_in[6];        // [40]
    float*       OUT = (float*)d_out;                // [100000,40]

    // one-time setup (first call is outside graph capture)
    static cudaStream_t s2 = nullptr;
    static cudaEvent_t evFork = nullptr, evJoin = nullptr;
    if (!s2) {
        cudaStreamCreateWithFlags(&s2, cudaStreamNonBlocking);
        cudaEventCreateWithFlags(&evFork, cudaEventDisableTiming);
        cudaEventCreateWithFlags(&evJoin, cudaEventDisableTiming);
        cudaFuncSetAttribute(gemm2_kernel,
                             cudaFuncAttributeMaxDynamicSharedMemorySize, G2_SMEM);
    }

    const int NB_SCAN = (N_NODES + 1023) / 1024;     // 98
    const int EB = E_EDGES / 256;                    // 6250 (exact)

    void* degPtr = nullptr;
    cudaGetSymbolAddress(&degPtr, g_deg);

    // ---- fork: CSR binning on s2, overlapped with gemm1 on stream 0 ----
    cudaEventRecord(evFork, 0);
    cudaStreamWaitEvent(s2, evFork, 0);

    cudaMemsetAsync(degPtr, 0, N_NODES * sizeof(int), s2);
    bin_count<<<EB, 256, 0, s2>>>(EI);
    scanA<<<NB_SCAN, 256, 0, s2>>>();
    scanB<<<1, 128, 0, s2>>>(NB_SCAN);
    scanC<<<NB_SCAN, 256, 0, s2>>>();
    bin_fill<<<EB, 256, 0, s2>>>(EI, EW);
    cudaEventRecord(evJoin, s2);

    // stream 0: W1 prep + GEMM1 (independent of binning)
    prep_w1<<<128, 256>>>(W1);
    gemm1_mma<<<(N_NODES + 127) / 128, 256>>>(X);

    // ---- join ----
    cudaStreamWaitEvent(0, evJoin, 0);

    // Agg1 (fused b1 + relu): agg1 = relu(S(m1) + b1)
    agg1_kernel<<<(N_NODES + 7) / 8, 256>>>(B1);

    // GEMM2: m2 = agg1 @ W2
    gemm2_kernel<<<(N_NODES + 127) / 128, 256, G2_SMEM>>>(W2);

    // Agg2 + b2 + log_softmax fused, writes d_out
    agg2_ls_kernel<<<(N_NODES + 7) / 8, 256>>>(B2, OUT);
}

// round 14
// speedup vs baseline: 2.6235x; 1.3945x over previous
#include <cuda_runtime.h>
#include <cuda_fp16.h>
#include <cstdint>

#define N_NODES 100000
#define E_EDGES 1600000
#define F_IN    512
#define F_HID   128
#define F_OUT   40

// Scratch (allocation-free rule: __device__ globals)
__device__ uint32_t g_m1h[(size_t)N_NODES * 64];   // X@W1 as half2-packed fp16
__device__ float g_agg1[(size_t)N_NODES * F_HID];  // relu(scatter-sum + b1), fp32
__device__ float g_m2[(size_t)N_NODES * F_OUT];    // h @ W2

// W1 fp16, pair-packed: [k2][n] uint32 = (fp16(W[2k2][n]), fp16(W[2k2+1][n]))
__device__ uint32_t g_w1h[256 * 128];
// W2 fp16, [n][k2] pair-packed: uint32 = (fp16(W2[2k2][n]), fp16(W2[2k2+1][n]))
__device__ uint32_t g_w2h[40 * 64];

// CSR binning scratch (rebuilt every launch)
__device__ int   g_deg[N_NODES];
__device__ int   g_off[N_NODES];
__device__ int   g_cur[N_NODES];
__device__ int   g_bsum[128];
__device__ int   g_bscan[128];
__device__ int   g_esrc[E_EDGES];
__device__ float g_ewp[E_EDGES];

// ============================================================================
// helpers
// ============================================================================
__device__ __forceinline__ void mma16816h(float* d, const uint32_t* a,
                                          uint32_t b0, uint32_t b1) {
    asm volatile(
        "mma.sync.aligned.m16n8k16.row.col.f32.f16.f16.f32 "
        "{%0,%1,%2,%3}, {%4,%5,%6,%7}, {%8,%9}, {%0,%1,%2,%3};"
        : "+f"(d[0]), "+f"(d[1]), "+f"(d[2]), "+f"(d[3])
        : "r"(a[0]), "r"(a[1]), "r"(a[2]), "r"(a[3]), "r"(b0), "r"(b1));
}

__device__ __forceinline__ void ldmx4(uint32_t* r, uint32_t addr) {
    asm volatile(
        "ldmatrix.sync.aligned.m8n8.x4.shared.b16 {%0,%1,%2,%3}, [%4];"
        : "=r"(r[0]), "=r"(r[1]), "=r"(r[2]), "=r"(r[3]) : "r"(addr));
}
__device__ __forceinline__ void ldmx2(uint32_t* r, uint32_t addr) {
    asm volatile(
        "ldmatrix.sync.aligned.m8n8.x2.shared.b16 {%0,%1}, [%2];"
        : "=r"(r[0]), "=r"(r[1]) : "r"(addr));
}

// fp16 hi/lo split of a pair of floats (packed half2 as uint32)
__device__ __forceinline__ void split2h(float x, float y,
                                        uint32_t& hi, uint32_t& lo) {
    __half2 h = __floats2half2_rn(x, y);
    float hx = __half2float(__low2half(h)), hy = __half2float(__high2half(h));
    __half2 l = __floats2half2_rn(x - hx, y - hy);
    hi = *(uint32_t*)&h;
    lo = *(uint32_t*)&l;
}

// ============================================================================
// prep_w1 / prep_w2: one-time fp16 packing of weights
// ============================================================================
__global__ __launch_bounds__(256) void prep_w1(const float* __restrict__ W1) {
    int i = blockIdx.x * 256 + threadIdx.x;   // i = k2*128 + n
    int k2 = i >> 7, n = i & 127;
    float w0 = W1[(size_t)(2 * k2) * F_HID + n];
    float w1 = W1[(size_t)(2 * k2 + 1) * F_HID + n];
    __half2 h = __floats2half2_rn(w0, w1);
    g_w1h[i] = *(uint32_t*)&h;
}

__global__ __launch_bounds__(256) void prep_w2(const float* __restrict__ W2) {
    int i = blockIdx.x * 256 + threadIdx.x;   // i = n*64 + k2
    if (i >= 40 * 64) return;
    int n = i >> 6, k2 = i & 63;
    float w0 = W2[(size_t)(2 * k2) * F_OUT + n];
    float w1 = W2[(size_t)(2 * k2 + 1) * F_OUT + n];
    __half2 h = __floats2half2_rn(w0, w1);
    g_w2h[i] = *(uint32_t*)&h;
}

// ============================================================================
// GEMM1 (mma.sync fp16, 2-term split): m1h[N,128] = X[N,512] @ W1[512,128]
// Block 128x128, BK=32, 8 warps (4m x 2n), sw-pipelined LDG, ldmatrix frags.
// Output stored as fp16 (half2-packed).
// ============================================================================
#define A_STRIDE 40   // 80B rows -> ldmatrix 8-row groups hit distinct banks
#define B_STRIDE 40

__global__ __launch_bounds__(256) void gemm1_mma(const float* __restrict__ X) {
    __shared__ __align__(16) unsigned short Ahi[128 * A_STRIDE];
    __shared__ __align__(16) unsigned short Alo[128 * A_STRIDE];
    __shared__ __align__(16) unsigned short Bh[128 * B_STRIDE];

    int tid = threadIdx.x;
    int wid = tid >> 5, lane = tid & 31;
    int warp_m = wid >> 1;
    int warp_n = wid & 1;
    int mBase = blockIdx.x * 128;

    uint32_t sAhi = (uint32_t)__cvta_generic_to_shared(Ahi);
    uint32_t sAlo = (uint32_t)__cvta_generic_to_shared(Alo);
    uint32_t sBh  = (uint32_t)__cvta_generic_to_shared(Bh);

    int aRow = tid >> 3, aK4 = tid & 7;
    bool aValid[4];
    const float* aPtr[4];
    #pragma unroll
    for (int i = 0; i < 4; i++) {
        int row = aRow + 32 * i;
        int grow = mBase + row;
        aValid[i] = grow < N_NODES;
        aPtr[i] = X + (size_t)(aValid[i] ? grow : 0) * F_IN + aK4 * 4;
    }
    int bN = tid & 127, bK2 = tid >> 7;
    int g4 = lane >> 3, r8 = lane & 7;

    float acc[2][8][4];
    #pragma unroll
    for (int mt = 0; mt < 2; mt++)
        #pragma unroll
        for (int nt = 0; nt < 8; nt++)
            #pragma unroll
            for (int i = 0; i < 4; i++) acc[mt][nt][i] = 0.f;

    float4 aReg[4];
    uint32_t bReg[8];
    #pragma unroll
    for (int i = 0; i < 4; i++)
        aReg[i] = aValid[i] ? *(const float4*)(aPtr[i])
                            : make_float4(0.f, 0.f, 0.f, 0.f);
    #pragma unroll
    for (int i = 0; i < 8; i++)
        bReg[i] = g_w1h[(bK2 + 2 * i) * 128 + bN];

    for (int stage = 0; stage < 16; stage++) {
        #pragma unroll
        for (int i = 0; i < 4; i++) {
            uint32_t h0, l0, h1, l1;
            split2h(aReg[i].x, aReg[i].y, h0, l0);
            split2h(aReg[i].z, aReg[i].w, h1, l1);
            int si = (aRow + 32 * i) * A_STRIDE + aK4 * 4;
            *(uint2*)&Ahi[si] = make_uint2(h0, h1);
            *(uint2*)&Alo[si] = make_uint2(l0, l1);
        }
        #pragma unroll
        for (int i = 0; i < 8; i++) {
            int si = bN * B_STRIDE + 2 * (bK2 + 2 * i);
            *(uint32_t*)&Bh[si] = bReg[i];
        }
        __syncthreads();

        if (stage < 15) {
            int kBase = (stage + 1) * 32;
            #pragma unroll
            for (int i = 0; i < 4; i++)
                aReg[i] = aValid[i] ? *(const float4*)(aPtr[i] + kBase)
                                    : make_float4(0.f, 0.f, 0.f, 0.f);
            #pragma unroll
            for (int i = 0; i < 8; i++)
                bReg[i] = g_w1h[(kBase / 2 + bK2 + 2 * i) * 128 + bN];
        }

        #pragma unroll
        for (int ks = 0; ks < 2; ks++) {
            int kk = ks * 16;
            int aSrcRow = (g4 & 1) * 8 + r8;
            int aSrcCol = kk + (g4 >> 1) * 8;
            uint32_t ah[2][4], al[2][4];
            #pragma unroll
            for (int mt = 0; mt < 2; mt++) {
                uint32_t off = ((warp_m * 32 + mt * 16 + aSrcRow) * A_STRIDE + aSrcCol) * 2;
                ldmx4(ah[mt], sAhi + off);
                ldmx4(al[mt], sAlo + off);
            }
            int bSrcN = (g4 >> 1) * 8 + r8;
            int bSrcK = kk + (g4 & 1) * 8;
            #pragma unroll
            for (int nt2 = 0; nt2 < 4; nt2++) {
                uint32_t b[4];
                uint32_t off = ((warp_n * 64 + nt2 * 16 + bSrcN) * B_STRIDE + bSrcK) * 2;
                ldmx4(b, sBh + off);
                #pragma unroll
                for (int mt = 0; mt < 2; mt++) {
                    mma16816h(acc[mt][2 * nt2 + 0], ah[mt], b[0], b[1]);
                    mma16816h(acc[mt][2 * nt2 + 0], al[mt], b[0], b[1]);
                    mma16816h(acc[mt][2 * nt2 + 1], ah[mt], b[2], b[3]);
                    mma16816h(acc[mt][2 * nt2 + 1], al[mt], b[2], b[3]);
                }
            }
        }
        __syncthreads();
    }

    // epilogue: pack to fp16 half2, store u32
    int g = lane >> 2, tg = lane & 3;
    #pragma unroll
    for (int mt = 0; mt < 2; mt++) {
        int r0 = mBase + warp_m * 32 + mt * 16 + g;
        int r1 = r0 + 8;
        #pragma unroll
        for (int nt = 0; nt < 8; nt++) {
            int col2 = warp_n * 32 + nt * 4 + tg;   // u32 index within row
            __half2 p0 = __floats2half2_rn(acc[mt][nt][0], acc[mt][nt][1]);
            __half2 p1 = __floats2half2_rn(acc[mt][nt][2], acc[mt][nt][3]);
            if (r0 < N_NODES) g_m1h[(size_t)r0 * 64 + col2] = *(uint32_t*)&p0;
            if (r1 < N_NODES) g_m1h[(size_t)r1 * 64 + col2] = *(uint32_t*)&p1;
        }
    }
}

// ============================================================================
// CSR binning: histogram -> exclusive scan -> placement
// ============================================================================
__global__ __launch_bounds__(256) void bin_count(const int* __restrict__ ei) {
    int e = blockIdx.x * 256 + threadIdx.x;
    if (e < E_EDGES) atomicAdd(&g_deg[ei[E_EDGES + e]], 1);
}

__global__ __launch_bounds__(256) void scanA() {
    __shared__ int wsum[8];
    int t = threadIdx.x;
    int base = blockIdx.x * 1024 + t * 4;
    int v[4];
    #pragma unroll
    for (int i = 0; i < 4; i++)
        v[i] = (base + i < N_NODES) ? g_deg[base + i] : 0;
    int s = v[0] + v[1] + v[2] + v[3];
    int lane = t & 31, w = t >> 5;
    int inc = s;
    #pragma unroll
    for (int o = 1; o < 32; o <<= 1) {
        int n = __shfl_up_sync(0xFFFFFFFFu, inc, o);
        if (lane >= o) inc += n;
    }
    if (lane == 31) wsum[w] = inc;
    __syncthreads();
    if (t == 0) {
        int run = 0;
        #pragma unroll
        for (int i = 0; i < 8; i++) { int x = wsum[i]; wsum[i] = run; run += x; }
        g_bsum[blockIdx.x] = run;
    }
    __syncthreads();
    int excl = inc - s + wsum[w];
    int o0 = excl, o1 = o0 + v[0], o2 = o1 + v[1], o3 = o2 + v[2];
    if (base + 0 < N_NODES) g_off[base + 0] = o0;
    if (base + 1 < N_NODES) g_off[base + 1] = o1;
    if (base + 2 < N_NODES) g_off[base + 2] = o2;
    if (base + 3 < N_NODES) g_off[base + 3] = o3;
}

__global__ __launch_bounds__(128) void scanB(int nb) {
    __shared__ int ws[4];
    int t = threadIdx.x;
    int v = (t < nb) ? g_bsum[t] : 0;
    int lane = t & 31, w = t >> 5;
    int inc = v;
    #pragma unroll
    for (int o = 1; o < 32; o <<= 1) {
        int n = __shfl_up_sync(0xFFFFFFFFu, inc, o);
        if (lane >= o) inc += n;
    }
    if (lane == 31) ws[w] = inc;
    __syncthreads();
    if (t == 0) {
        int run = 0;
        #pragma unroll
        for (int i = 0; i < 4; i++) { int x = ws[i]; ws[i] = run; run += x; }
    }
    __syncthreads();
    if (t < nb) g_bscan[t] = inc - v + ws[w];
}

__global__ __launch_bounds__(256) void scanC() {
    int add = g_bscan[blockIdx.x];
    int base = blockIdx.x * 1024 + threadIdx.x;
    #pragma unroll
    for (int i = 0; i < 4; i++) {
        int idx = base + i * 256;
        if (idx < N_NODES) {
            int val = g_off[idx] + add;
            g_off[idx] = val;
            g_cur[idx] = val;
        }
    }
}

__global__ __launch_bounds__(256) void bin_fill(const int* __restrict__ ei,
                                                const float* __restrict__ ew) {
    int e = blockIdx.x * 256 + threadIdx.x;
    if (e >= E_EDGES) return;
    int src = ei[e];
    int dst = ei[E_EDGES + e];
    int pos = atomicAdd(&g_cur[dst], 1);
    g_esrc[pos] = src;
    g_ewp[pos] = ew[e];
}

// ============================================================================
// Agg1 (dst-driven, fused b1+relu), fp16 m1 gather, 4-deep unroll
// ============================================================================
__global__ __launch_bounds__(256) void agg1_kernel(const float* __restrict__ b1) {
    int wv = blockIdx.x * 8 + (threadIdx.x >> 5);
    int lane = threadIdx.x & 31;
    if (wv >= N_NODES) return;
    int beg = g_off[wv];
    int end = (wv == N_NODES - 1) ? E_EDGES : g_off[wv + 1];

    float4 a0 = make_float4(0.f, 0.f, 0.f, 0.f);
    float4 a1 = make_float4(0.f, 0.f, 0.f, 0.f);
    float4 a2 = make_float4(0.f, 0.f, 0.f, 0.f);
    float4 a3 = make_float4(0.f, 0.f, 0.f, 0.f);
    int j = beg;
    for (; j + 4 <= end; j += 4) {
        int s0 = g_esrc[j], s1 = g_esrc[j + 1], s2 = g_esrc[j + 2], s3 = g_esrc[j + 3];
        float w0 = g_ewp[j], w1 = g_ewp[j + 1], w2 = g_ewp[j + 2], w3 = g_ewp[j + 3];
        uint2 q0 = ((const uint2*)(g_m1h + (size_t)s0 * 64))[lane];
        uint2 q1 = ((const uint2*)(g_m1h + (size_t)s1 * 64))[lane];
        uint2 q2 = ((const uint2*)(g_m1h + (size_t)s2 * 64))[lane];
        uint2 q3 = ((const uint2*)(g_m1h + (size_t)s3 * 64))[lane];
        float2 u, v;
        u = __half22float2(*(__half2*)&q0.x); v = __half22float2(*(__half2*)&q0.y);
        a0.x += u.x * w0; a0.y += u.y * w0; a0.z += v.x * w0; a0.w += v.y * w0;
        u = __half22float2(*(__half2*)&q1.x); v = __half22float2(*(__half2*)&q1.y);
        a1.x += u.x * w1; a1.y += u.y * w1; a1.z += v.x * w1; a1.w += v.y * w1;
        u = __half22float2(*(__half2*)&q2.x); v = __half22float2(*(__half2*)&q2.y);
        a2.x += u.x * w2; a2.y += u.y * w2; a2.z += v.x * w2; a2.w += v.y * w2;
        u = __half22float2(*(__half2*)&q3.x); v = __half22float2(*(__half2*)&q3.y);
        a3.x += u.x * w3; a3.y += u.y * w3; a3.z += v.x * w3; a3.w += v.y * w3;
    }
    for (; j < end; j++) {
        int s0 = g_esrc[j];
        float w0 = g_ewp[j];
        uint2 q0 = ((const uint2*)(g_m1h + (size_t)s0 * 64))[lane];
        float2 u = __half22float2(*(__half2*)&q0.x);
        float2 v = __half22float2(*(__half2*)&q0.y);
        a0.x += u.x * w0; a0.y += u.y * w0; a0.z += v.x * w0; a0.w += v.y * w0;
    }
    float4 bb = ((const float4*)b1)[lane];
    float4 r;
    r.x = fmaxf(a0.x + a1.x + a2.x + a3.x + bb.x, 0.f);
    r.y = fmaxf(a0.y + a1.y + a2.y + a3.y + bb.y, 0.f);
    r.z = fmaxf(a0.z + a1.z + a2.z + a3.z + bb.z, 0.f);
    r.w = fmaxf(a0.w + a1.w + a2.w + a3.w + bb.w, 0.f);
    ((float4*)(g_agg1 + (size_t)wv * F_HID))[lane] = r;
}

// ============================================================================
// GEMM2 (mma fp16 2-term): g_m2[N,40] = agg1 @ W2[128,40]
// Block 128 rows, K=128 fully staged; 8 warps x 16 rows; 5 n8 tiles.
// ============================================================================
#define G2K 136   // smem row stride in shorts (272B: 8-row groups conflict-free)
#define G2M_SMEM ((2 * 128 * G2K + 40 * G2K) * 2)

__global__ __launch_bounds__(256) void gemm2_mma() {
    extern __shared__ unsigned short g2sm[];
    unsigned short* Ahi = g2sm;                    // [128][G2K]
    unsigned short* Alo = g2sm + 128 * G2K;
    uint32_t* Bh32 = (uint32_t*)(g2sm + 2 * 128 * G2K);   // [40][G2K/2]

    int tid = threadIdx.x, wid = tid >> 5, lane = tid & 31;
    int rowBase = blockIdx.x * 128;

    // W2 fp16 -> smem [n][k] stride G2K
    #pragma unroll
    for (int i = 0; i < 10; i++) {
        int idx = tid + 256 * i;
        int n = idx >> 6, k2 = idx & 63;
        Bh32[n * (G2K / 2) + k2] = g_w2h[idx];
    }
    // agg1 rows -> hi/lo fp16 smem
    #pragma unroll
    for (int i = 0; i < 16; i++) {
        int idx = tid + 256 * i;            // 4096 float4s
        int r = idx >> 5, k4 = idx & 31;
        int row = rowBase + r;
        float4 v = make_float4(0.f, 0.f, 0.f, 0.f);
        if (row < N_NODES)
            v = ((const float4*)(g_agg1 + (size_t)row * F_HID))[k4];
        uint32_t h0, l0, h1, l1;
        split2h(v.x, v.y, h0, l0);
        split2h(v.z, v.w, h1, l1);
        int si = r * G2K + k4 * 4;
        *(uint2*)&Ahi[si] = make_uint2(h0, h1);
        *(uint2*)&Alo[si] = make_uint2(l0, l1);
    }
    __syncthreads();

    uint32_t sbase = (uint32_t)__cvta_generic_to_shared(g2sm);
    uint32_t sAhi = sbase;
    uint32_t sAlo = sbase + 128 * G2K * 2;
    uint32_t sBh  = sbase + 2 * 128 * G2K * 2;

    float acc[5][4];
    #pragma unroll
    for (int nt = 0; nt < 5; nt++)
        #pragma unroll
        for (int i = 0; i < 4; i++) acc[nt][i] = 0.f;

    int g4 = lane >> 3, r8 = lane & 7;
    int aSrcRow = (g4 & 1) * 8 + r8;
    int aColSel = (g4 >> 1) * 8;
    int bSrcN = (g4 >> 1) * 8 + r8;
    int bKSel = (g4 & 1) * 8;
    int b2N = lane & 7, b2KSel = ((lane >> 3) & 1) * 8;

    #pragma unroll
    for (int ks = 0; ks < 8; ks++) {
        int kk = ks * 16;
        uint32_t ah[4], al[4];
        uint32_t aoff = ((wid * 16 + aSrcRow) * G2K + kk + aColSel) * 2;
        ldmx4(ah, sAhi + aoff);
        ldmx4(al, sAlo + aoff);
        uint32_t b[4];
        uint32_t boff = ((bSrcN) * G2K + kk + bKSel) * 2;         // n tiles 0,1
        ldmx4(b, sBh + boff);
        mma16816h(acc[0], ah, b[0], b[1]);
        mma16816h(acc[0], al, b[0], b[1]);
        mma16816h(acc[1], ah, b[2], b[3]);
        mma16816h(acc[1], al, b[2], b[3]);
        boff = ((16 + bSrcN) * G2K + kk + bKSel) * 2;             // n tiles 2,3
        ldmx4(b, sBh + boff);
        mma16816h(acc[2], ah, b[0], b[1]);
        mma16816h(acc[2], al, b[0], b[1]);
        mma16816h(acc[3], ah, b[2], b[3]);
        mma16816h(acc[3], al, b[2], b[3]);
        uint32_t b2[2];
        uint32_t boff2 = ((32 + b2N) * G2K + kk + b2KSel) * 2;    // n tile 4
        ldmx2(b2, sBh + boff2);
        mma16816h(acc[4], ah, b2[0], b2[1]);
        mma16816h(acc[4], al, b2[0], b2[1]);
    }

    int g = lane >> 2, tg = lane & 3;
    int r0 = rowBase + wid * 16 + g, r1 = r0 + 8;
    #pragma unroll
    for (int nt = 0; nt < 5; nt++) {
        int col = nt * 8 + 2 * tg;
        if (r0 < N_NODES)
            *(float2*)(g_m2 + (size_t)r0 * F_OUT + col) = make_float2(acc[nt][0], acc[nt][1]);
        if (r1 < N_NODES)
            *(float2*)(g_m2 + (size_t)r1 * F_OUT + col) = make_float2(acc[nt][2], acc[nt][3]);
    }
}

// ============================================================================
// Agg2 + b2 + log_softmax fused (dst-driven), 4-deep unroll
// ============================================================================
__global__ __launch_bounds__(256) void agg2_ls_kernel(const float* __restrict__ b2,
                                                      float* __restrict__ out) {
    int wv = blockIdx.x * 8 + (threadIdx.x >> 5);
    int lane = threadIdx.x & 31;
    if (wv >= N_NODES) return;
    int beg = g_off[wv];
    int end = (wv == N_NODES - 1) ? E_EDGES : g_off[wv + 1];
    bool act = lane < 10;

    float4 a0 = make_float4(0.f, 0.f, 0.f, 0.f);
    float4 a1 = make_float4(0.f, 0.f, 0.f, 0.f);
    float4 a2 = make_float4(0.f, 0.f, 0.f, 0.f);
    float4 a3 = make_float4(0.f, 0.f, 0.f, 0.f);
    int j = beg;
    for (; j + 4 <= end; j += 4) {
        int s0 = g_esrc[j], s1 = g_esrc[j + 1], s2 = g_esrc[j + 2], s3 = g_esrc[j + 3];
        float w0 = g_ewp[j], w1 = g_ewp[j + 1], w2 = g_ewp[j + 2], w3 = g_ewp[j + 3];
        if (act) {
            float4 m0 = ((const float4*)(g_m2 + (size_t)s0 * F_OUT))[lane];
            float4 m1v = ((const float4*)(g_m2 + (size_t)s1 * F_OUT))[lane];
            float4 m2v = ((const float4*)(g_m2 + (size_t)s2 * F_OUT))[lane];
            float4 m3v = ((const float4*)(g_m2 + (size_t)s3 * F_OUT))[lane];
            a0.x += m0.x * w0; a0.y += m0.y * w0; a0.z += m0.z * w0; a0.w += m0.w * w0;
            a1.x += m1v.x * w1; a1.y += m1v.y * w1; a1.z += m1v.z * w1; a1.w += m1v.w * w1;
            a2.x += m2v.x * w2; a2.y += m2v.y * w2; a2.z += m2v.z * w2; a2.w += m2v.w * w2;
            a3.x += m3v.x * w3; a3.y += m3v.y * w3; a3.z += m3v.z * w3; a3.w += m3v.w * w3;
        }
    }
    for (; j < end; j++) {
        int s0 = g_esrc[j];
        float w0 = g_ewp[j];
        if (act) {
            float4 m0 = ((const float4*)(g_m2 + (size_t)s0 * F_OUT))[lane];
            a0.x += m0.x * w0; a0.y += m0.y * w0; a0.z += m0.z * w0; a0.w += m0.w * w0;
        }
    }
    float4 x = make_float4(a0.x + a1.x + a2.x + a3.x, a0.y + a1.y + a2.y + a3.y,
                           a0.z + a1.z + a2.z + a3.z, a0.w + a1.w + a2.w + a3.w);
    if (act) {
        float4 bb = ((const float4*)b2)[lane];
        x.x += bb.x; x.y += bb.y; x.z += bb.z; x.w += bb.w;
    }

    float m = act ? fmaxf(fmaxf(x.x, x.y), fmaxf(x.z, x.w)) : -1e30f;
    #pragma unroll
    for (int o = 16; o; o >>= 1) m = fmaxf(m, __shfl_xor_sync(0xFFFFFFFFu, m, o));

    float s = act ? (__expf(x.x - m) + __expf(x.y - m) +
                     __expf(x.z - m) + __expf(x.w - m)) : 0.f;
    #pragma unroll
    for (int o = 16; o; o >>= 1) s += __shfl_xor_sync(0xFFFFFFFFu, s, o);

    float lse = m + __logf(s);
    if (act) {
        x.x -= lse; x.y -= lse; x.z -= lse; x.w -= lse;
        ((float4*)(out + (size_t)wv * F_OUT))[lane] = x;
    }
}

// ============================================================================
extern "C" void kernel_launch(void* const* d_in, const int* in_sizes, int n_in,
                              void* d_out, int out_size) {
    const float* X   = (const float*)d_in[0];        // [100000,512]
    const int*   EI  = (const int*)d_in[1];          // [2,1600000] int32
    const float* EW  = (const float*)d_in[2];        // [1600000]
    const float* W1  = (const float*)d_in[3];        // [512,128]
    const float* B1  = (const float*)d_in[4];        // [128]
    const float* W2  = (const float*)d_in[5];        // [128,40]
    const float* B2  = (const float*)d_in[6];        // [40]
    float*       OUT = (float*)d_out;                // [100000,40]

    // one-time setup (first call is outside graph capture)
    static cudaStream_t s2 = nullptr;
    static cudaEvent_t evFork = nullptr, evJoin = nullptr;
    if (!s2) {
        cudaStreamCreateWithFlags(&s2, cudaStreamNonBlocking);
        cudaEventCreateWithFlags(&evFork, cudaEventDisableTiming);
        cudaEventCreateWithFlags(&evJoin, cudaEventDisableTiming);
        cudaFuncSetAttribute(gemm2_mma,
                             cudaFuncAttributeMaxDynamicSharedMemorySize, G2M_SMEM);
    }

    const int NB_SCAN = (N_NODES + 1023) / 1024;     // 98
    const int EB = E_EDGES / 256;                    // 6250 (exact)

    void* degPtr = nullptr;
    cudaGetSymbolAddress(&degPtr, g_deg);

    // ---- fork: CSR binning on s2, overlapped with gemm1 on stream 0 ----
    cudaEventRecord(evFork, 0);
    cudaStreamWaitEvent(s2, evFork, 0);

    cudaMemsetAsync(degPtr, 0, N_NODES * sizeof(int), s2);
    bin_count<<<EB, 256, 0, s2>>>(EI);
    scanA<<<NB_SCAN, 256, 0, s2>>>();
    scanB<<<1, 128, 0, s2>>>(NB_SCAN);
    scanC<<<NB_SCAN, 256, 0, s2>>>();
    bin_fill<<<EB, 256, 0, s2>>>(EI, EW);
    cudaEventRecord(evJoin, s2);

    // stream 0: weight prep + GEMM1 (independent of binning)
    prep_w1<<<128, 256>>>(W1);
    prep_w2<<<10, 256>>>(W2);
    gemm1_mma<<<(N_NODES + 127) / 128, 256>>>(X);

    // ---- join ----
    cudaStreamWaitEvent(0, evJoin, 0);

    // Agg1 (fused b1 + relu): agg1 = relu(S(m1) + b1)
    agg1_kernel<<<(N_NODES + 7) / 8, 256>>>(B1);

    // GEMM2 (tensor): m2 = agg1 @ W2
    gemm2_mma<<<(N_NODES + 127) / 128, 256, G2M_SMEM>>>();

    // Agg2 + b2 + log_softmax fused, writes d_out
    agg2_ls_kernel<<<(N_NODES + 7) / 8, 256>>>(B2, OUT);
}